// round 2
// baseline (speedup 1.0000x reference)
#include <cuda_runtime.h>
#include <cuda_bf16.h>

#define NN   50000
#define EE   400000
#define ET   (EE + NN)      // 450000 edges incl self-loops
#define DIN  128
#define H1N  8
#define C1N  64
#define F1   512            // H1N*C1N
#define C2N  16

typedef unsigned long long ull;

// ------------------------- scratch (static device memory) -------------------
__device__ float g_h1[(size_t)NN * F1];     // layer-1 transformed features
__device__ float g_out1[(size_t)NN * F1];   // elu(layer-1 output)
__device__ float g_h2[(size_t)NN * C2N];    // layer-2 transformed features
__device__ float g_al1s[NN * H1N];
__device__ float g_al1d[NN * H1N];
__device__ float g_al2s[NN];
__device__ float g_al2d[NN];
__device__ int   g_deg[NN];
__device__ int   g_cur[NN];
__device__ int   g_off[NN + 1];
__device__ int   g_bsums[64];
__device__ int   g_esrc[ET];

// ------------------------- small helpers ------------------------------------
__device__ __forceinline__ ull pack2(float lo, float hi) {
    ull r; asm("mov.b64 %0,{%1,%2};" : "=l"(r) : "f"(lo), "f"(hi)); return r;
}
__device__ __forceinline__ void unpack2(ull v, float& lo, float& hi) {
    asm("mov.b64 {%0,%1},%2;" : "=f"(lo), "=f"(hi) : "l"(v));
}
__device__ __forceinline__ ull fma2(ull a, ull b, ull c) {
    ull d; asm("fma.rn.f32x2 %0,%1,%2,%3;" : "=l"(d) : "l"(a), "l"(b), "l"(c)); return d;
}
__device__ __forceinline__ float lrelu(float x) { return x > 0.f ? x : 0.2f * x; }
__device__ __forceinline__ float eluf(float x)  { return x > 0.f ? x : (__expf(x) - 1.f); }

// ------------------------- CSR construction ---------------------------------
__global__ void k_zero() {
    int i = blockIdx.x * blockDim.x + threadIdx.x;
    if (i < NN) g_deg[i] = 0;
}

__global__ void k_deg(const int* __restrict__ ei) {
    int e = blockIdx.x * blockDim.x + threadIdx.x;
    if (e >= ET) return;
    int d = (e < EE) ? ei[EE + e] : (e - EE);
    atomicAdd(&g_deg[d], 1);
}

__global__ void k_scan1() {
    __shared__ int sh[1024];
    int i = blockIdx.x * 1024 + threadIdx.x;
    int v = (i < NN) ? g_deg[i] : 0;
    sh[threadIdx.x] = v;
    __syncthreads();
    #pragma unroll
    for (int ofs = 1; ofs < 1024; ofs <<= 1) {
        int t = 0;
        if ((int)threadIdx.x >= ofs) t = sh[threadIdx.x - ofs];
        __syncthreads();
        sh[threadIdx.x] += t;
        __syncthreads();
    }
    if (i < NN) g_off[i] = sh[threadIdx.x] - v;        // exclusive within block
    if (threadIdx.x == 1023) g_bsums[blockIdx.x] = sh[1023];
}

__global__ void k_scan2() {
    if (threadIdx.x == 0) {
        int run = 0;
        for (int i = 0; i < 49; i++) { int t = g_bsums[i]; g_bsums[i] = run; run += t; }
    }
}

__global__ void k_scan3() {
    int i = blockIdx.x * 1024 + threadIdx.x;
    if (i < NN) {
        int o = g_off[i] + g_bsums[blockIdx.x];
        g_off[i] = o;
        g_cur[i] = o;
    }
    if (i == 0) g_off[NN] = ET;
}

__global__ void k_fill(const int* __restrict__ ei) {
    int e = blockIdx.x * blockDim.x + threadIdx.x;
    if (e >= ET) return;
    int s = (e < EE) ? ei[e] : (e - EE);
    int d = (e < EE) ? ei[EE + e] : (e - EE);
    int p = atomicAdd(&g_cur[d], 1);
    g_esrc[p] = s;
}

// ------------------------- GEMM1: h1 = x @ W1  (N x 128 x 512) --------------
// 128x128 tile, BK=16, 256 threads, 8x8 microtile, packed f32x2 FMAs.
__global__ __launch_bounds__(256, 2) void k_gemm1(const float* __restrict__ x,
                                                  const float* __restrict__ w) {
    __shared__ __align__(16) float As[16][132];  // [k][row], padded
    __shared__ __align__(16) float Bs[16][128];  // [k][col]
    int tid = threadIdx.x;
    int r0 = blockIdx.x * 128, c0 = blockIdx.y * 128;
    int tx = tid & 15, ty = tid >> 4;

    ull acc[8][4];
    #pragma unroll
    for (int i = 0; i < 8; i++)
        #pragma unroll
        for (int j = 0; j < 4; j++) acc[i][j] = 0ULL;

    int arow = tid >> 2;   // 0..63
    int aq   = tid & 3;    // which float4 within the 16-wide k chunk
    int bk   = tid >> 5;   // 0..7
    int bq   = tid & 31;   // col quad

    for (int kb = 0; kb < 8; kb++) {
        int k0 = kb * 16;
        #pragma unroll
        for (int l = 0; l < 2; l++) {
            int row = arow + l * 64;
            int gr  = r0 + row;
            float4 v = make_float4(0.f, 0.f, 0.f, 0.f);
            if (gr < NN) v = *(const float4*)&x[(size_t)gr * DIN + k0 + aq * 4];
            As[aq * 4 + 0][row] = v.x;
            As[aq * 4 + 1][row] = v.y;
            As[aq * 4 + 2][row] = v.z;
            As[aq * 4 + 3][row] = v.w;
        }
        #pragma unroll
        for (int l = 0; l < 2; l++) {
            int k = bk + l * 8;
            float4 v = *(const float4*)&w[(size_t)(k0 + k) * F1 + c0 + bq * 4];
            *(float4*)&Bs[k][bq * 4] = v;
        }
        __syncthreads();
        #pragma unroll
        for (int kk = 0; kk < 16; kk++) {
            float4 a0 = *(float4*)&As[kk][ty * 8];
            float4 a1 = *(float4*)&As[kk][ty * 8 + 4];
            float4 b0 = *(float4*)&Bs[kk][tx * 8];
            float4 b1 = *(float4*)&Bs[kk][tx * 8 + 4];
            ull bp[4] = { pack2(b0.x, b0.y), pack2(b0.z, b0.w),
                          pack2(b1.x, b1.y), pack2(b1.z, b1.w) };
            float av[8] = { a0.x, a0.y, a0.z, a0.w, a1.x, a1.y, a1.z, a1.w };
            #pragma unroll
            for (int i = 0; i < 8; i++) {
                ull ap = pack2(av[i], av[i]);
                #pragma unroll
                for (int j = 0; j < 4; j++) acc[i][j] = fma2(ap, bp[j], acc[i][j]);
            }
        }
        __syncthreads();
    }
    #pragma unroll
    for (int i = 0; i < 8; i++) {
        int gr = r0 + ty * 8 + i;
        if (gr >= NN) continue;
        float o[8];
        #pragma unroll
        for (int j = 0; j < 4; j++) unpack2(acc[i][j], o[2 * j], o[2 * j + 1]);
        float* dst = &g_h1[(size_t)gr * F1 + c0 + tx * 8];
        *(float4*)dst       = make_float4(o[0], o[1], o[2], o[3]);
        *(float4*)(dst + 4) = make_float4(o[4], o[5], o[6], o[7]);
    }
}

// ------------------------- per-node attention halves (layer 1) --------------
__global__ __launch_bounds__(256) void k_al1(const float* __restrict__ a1s,
                                             const float* __restrict__ a1d) {
    __shared__ float s_as[F1], s_ad[F1];
    int tid = threadIdx.x;
    for (int i = tid; i < F1; i += 256) { s_as[i] = a1s[i]; s_ad[i] = a1d[i]; }
    __syncthreads();
    int wid = tid >> 5, lane = tid & 31;
    int n = blockIdx.x * 8 + wid;
    const float4* hp = (const float4*)&g_h1[(size_t)n * F1];
    float ps[4], pd[4];
    #pragma unroll
    for (int j = 0; j < 4; j++) {
        float4 v = hp[lane + 32 * j];
        int ch = lane * 4 + 128 * j;   // linear channel == h*64+c (matches a layout)
        float4 a = *(float4*)&s_as[ch];
        float4 b = *(float4*)&s_ad[ch];
        ps[j] = v.x * a.x + v.y * a.y + v.z * a.z + v.w * a.w;
        pd[j] = v.x * b.x + v.y * b.y + v.z * b.z + v.w * b.w;
    }
    #pragma unroll
    for (int o = 8; o >= 1; o >>= 1) {
        #pragma unroll
        for (int j = 0; j < 4; j++) {
            ps[j] += __shfl_xor_sync(0xffffffffu, ps[j], o);
            pd[j] += __shfl_xor_sync(0xffffffffu, pd[j], o);
        }
    }
    if (lane == 0) {
        #pragma unroll
        for (int j = 0; j < 4; j++) { g_al1s[n * 8 + 2 * j] = ps[j]; g_al1d[n * 8 + 2 * j] = pd[j]; }
    }
    if (lane == 16) {
        #pragma unroll
        for (int j = 0; j < 4; j++) { g_al1s[n * 8 + 2 * j + 1] = ps[j]; g_al1d[n * 8 + 2 * j + 1] = pd[j]; }
    }
}

// ------------------------- layer-1 softmax + aggregation + ELU --------------
__global__ __launch_bounds__(256) void k_agg1(const float* __restrict__ b1) {
    __shared__ float sb1[F1];
    int tid = threadIdx.x;
    for (int i = tid; i < F1; i += 256) sb1[i] = b1[i];
    __syncthreads();
    int wid = tid >> 5, lane = tid & 31;
    int n = blockIdx.x * 8 + wid;
    int beg = g_off[n], end = g_off[n + 1];

    float ad[8];
    {
        const float4* p = (const float4*)&g_al1d[n * 8];
        float4 u = p[0], v = p[1];
        ad[0]=u.x; ad[1]=u.y; ad[2]=u.z; ad[3]=u.w; ad[4]=v.x; ad[5]=v.y; ad[6]=v.z; ad[7]=v.w;
    }
    float m[8];
    #pragma unroll
    for (int h = 0; h < 8; h++) m[h] = -1e30f;
    for (int e = beg + lane; e < end; e += 32) {
        int s = g_esrc[e];
        const float4* q = (const float4*)&g_al1s[s * 8];
        float4 u = q[0], v = q[1];
        float lg[8] = { u.x+ad[0], u.y+ad[1], u.z+ad[2], u.w+ad[3],
                        v.x+ad[4], v.y+ad[5], v.z+ad[6], v.w+ad[7] };
        #pragma unroll
        for (int h = 0; h < 8; h++) m[h] = fmaxf(m[h], lrelu(lg[h]));
    }
    #pragma unroll
    for (int o = 16; o >= 1; o >>= 1)
        #pragma unroll
        for (int h = 0; h < 8; h++) m[h] = fmaxf(m[h], __shfl_xor_sync(0xffffffffu, m[h], o));

    float sm[8];
    #pragma unroll
    for (int h = 0; h < 8; h++) sm[h] = 0.f;
    for (int e = beg + lane; e < end; e += 32) {
        int s = g_esrc[e];
        const float4* q = (const float4*)&g_al1s[s * 8];
        float4 u = q[0], v = q[1];
        float lg[8] = { u.x+ad[0], u.y+ad[1], u.z+ad[2], u.w+ad[3],
                        v.x+ad[4], v.y+ad[5], v.z+ad[6], v.w+ad[7] };
        #pragma unroll
        for (int h = 0; h < 8; h++) sm[h] += __expf(lrelu(lg[h]) - m[h]);
    }
    #pragma unroll
    for (int o = 16; o >= 1; o >>= 1)
        #pragma unroll
        for (int h = 0; h < 8; h++) sm[h] += __shfl_xor_sync(0xffffffffu, sm[h], o);
    float rs[8];
    #pragma unroll
    for (int h = 0; h < 8; h++) rs[h] = 1.f / sm[h];

    float4 acc[4];
    #pragma unroll
    for (int j = 0; j < 4; j++) acc[j] = make_float4(0.f, 0.f, 0.f, 0.f);
    int hi = lane >> 4;
    for (int e = beg; e < end; e++) {
        int s = g_esrc[e];
        float av = 0.f;
        if (lane < 8) {
            float t = g_al1s[s * 8 + lane] + ad[lane];
            t = lrelu(t);
            av = __expf(t - m[lane]) * rs[lane];
        }
        float al[8];
        #pragma unroll
        for (int h = 0; h < 8; h++) al[h] = __shfl_sync(0xffffffffu, av, h);
        const float4* hp = (const float4*)&g_h1[(size_t)s * F1];
        #pragma unroll
        for (int j = 0; j < 4; j++) {
            float4 v = hp[lane + 32 * j];
            float a = al[2 * j + hi];
            acc[j].x = fmaf(a, v.x, acc[j].x);
            acc[j].y = fmaf(a, v.y, acc[j].y);
            acc[j].z = fmaf(a, v.z, acc[j].z);
            acc[j].w = fmaf(a, v.w, acc[j].w);
        }
    }
    float4* op = (float4*)&g_out1[(size_t)n * F1];
    #pragma unroll
    for (int j = 0; j < 4; j++) {
        int ch = lane * 4 + 128 * j;
        float4 bb = *(float4*)&sb1[ch];
        float4 o;
        o.x = eluf(acc[j].x + bb.x);
        o.y = eluf(acc[j].y + bb.y);
        o.z = eluf(acc[j].z + bb.z);
        o.w = eluf(acc[j].w + bb.w);
        op[lane + 32 * j] = o;
    }
}

// ------------------------- GEMM2 + layer-2 attention halves -----------------
// one warp handles 2 nodes; W2 staged in smem with pad-20 rows.
__global__ __launch_bounds__(256) void k_gemm2(const float* __restrict__ W2,
                                               const float* __restrict__ a2s,
                                               const float* __restrict__ a2d) {
    __shared__ __align__(16) float sw[F1 * 20];
    __shared__ float sa2s[16], sa2d[16];
    int tid = threadIdx.x;
    for (int i = tid; i < F1 * C2N; i += 256) {
        int k = i >> 4, o = i & 15;
        sw[k * 20 + o] = W2[i];
    }
    if (tid < 16) { sa2s[tid] = a2s[tid]; sa2d[tid] = a2d[tid]; }
    __syncthreads();
    int wid = tid >> 5, lane = tid & 31;
    int n0 = (blockIdx.x * 8 + wid) * 2;
    const float* vA = &g_out1[(size_t)n0 * F1];
    const float* vB = vA + F1;
    float4 pA[4], pB[4];
    #pragma unroll
    for (int q = 0; q < 4; q++) { pA[q] = make_float4(0,0,0,0); pB[q] = make_float4(0,0,0,0); }
    #pragma unroll
    for (int j = 0; j < 16; j++) {
        int k = lane + 32 * j;
        float a = vA[k], b = vB[k];
        const float4* wr = (const float4*)&sw[k * 20];
        #pragma unroll
        for (int q = 0; q < 4; q++) {
            float4 w = wr[q];
            pA[q].x = fmaf(a, w.x, pA[q].x); pA[q].y = fmaf(a, w.y, pA[q].y);
            pA[q].z = fmaf(a, w.z, pA[q].z); pA[q].w = fmaf(a, w.w, pA[q].w);
            pB[q].x = fmaf(b, w.x, pB[q].x); pB[q].y = fmaf(b, w.y, pB[q].y);
            pB[q].z = fmaf(b, w.z, pB[q].z); pB[q].w = fmaf(b, w.w, pB[q].w);
        }
    }
    #pragma unroll
    for (int o = 16; o >= 1; o >>= 1) {
        #pragma unroll
        for (int q = 0; q < 4; q++) {
            pA[q].x += __shfl_xor_sync(0xffffffffu, pA[q].x, o);
            pA[q].y += __shfl_xor_sync(0xffffffffu, pA[q].y, o);
            pA[q].z += __shfl_xor_sync(0xffffffffu, pA[q].z, o);
            pA[q].w += __shfl_xor_sync(0xffffffffu, pA[q].w, o);
            pB[q].x += __shfl_xor_sync(0xffffffffu, pB[q].x, o);
            pB[q].y += __shfl_xor_sync(0xffffffffu, pB[q].y, o);
            pB[q].z += __shfl_xor_sync(0xffffffffu, pB[q].z, o);
            pB[q].w += __shfl_xor_sync(0xffffffffu, pB[q].w, o);
        }
    }
    if (lane < 2) {
        int n = n0 + lane;
        float4 P[4];
        #pragma unroll
        for (int q = 0; q < 4; q++) P[q] = lane ? pB[q] : pA[q];
        float4* ho = (float4*)&g_h2[(size_t)n * C2N];
        #pragma unroll
        for (int q = 0; q < 4; q++) ho[q] = P[q];
        float ds = 0.f, dd = 0.f;
        #pragma unroll
        for (int q = 0; q < 4; q++) {
            ds += P[q].x * sa2s[q*4+0] + P[q].y * sa2s[q*4+1] + P[q].z * sa2s[q*4+2] + P[q].w * sa2s[q*4+3];
            dd += P[q].x * sa2d[q*4+0] + P[q].y * sa2d[q*4+1] + P[q].z * sa2d[q*4+2] + P[q].w * sa2d[q*4+3];
        }
        g_al2s[n] = ds;
        g_al2d[n] = dd;
    }
}

// ------------------------- layer-2 softmax + aggregation + bias -------------
__global__ __launch_bounds__(256) void k_agg2(const float* __restrict__ b2,
                                              float* __restrict__ out) {
    int tid = threadIdx.x;
    int wid = tid >> 5, lane = tid & 31;
    int n = blockIdx.x * 8 + wid;
    int beg = g_off[n], end = g_off[n + 1];
    float adn = g_al2d[n];

    float m = -1e30f;
    for (int e = beg + lane; e < end; e += 32) {
        int s = g_esrc[e];
        m = fmaxf(m, lrelu(g_al2s[s] + adn));
    }
    #pragma unroll
    for (int o = 16; o >= 1; o >>= 1) m = fmaxf(m, __shfl_xor_sync(0xffffffffu, m, o));

    float sm = 0.f;
    for (int e = beg + lane; e < end; e += 32) {
        int s = g_esrc[e];
        sm += __expf(lrelu(g_al2s[s] + adn) - m);
    }
    #pragma unroll
    for (int o = 16; o >= 1; o >>= 1) sm += __shfl_xor_sync(0xffffffffu, sm, o);
    float rinv = 1.f / sm;

    int half = lane >> 4, hl = lane & 15;
    float acc = 0.f;
    for (int e2 = beg; e2 < end; e2 += 2) {
        int e = e2 + half;
        bool ok = (e < end);
        int s = 0;
        float av = 0.f;
        if (ok) s = g_esrc[e];
        if (ok && hl == 0) {
            float t = lrelu(g_al2s[s] + adn);
            av = __expf(t - m) * rinv;
        }
        av = __shfl_sync(0xffffffffu, av, half << 4);
        float v = ok ? g_h2[(size_t)s * C2N + hl] : 0.f;
        acc = fmaf(av, v, acc);
    }
    acc += __shfl_xor_sync(0xffffffffu, acc, 16);
    if (lane < 16) out[(size_t)n * C2N + lane] = acc + b2[lane];
}

// ------------------------- launch -------------------------------------------
extern "C" void kernel_launch(void* const* d_in, const int* in_sizes, int n_in,
                              void* d_out, int out_size) {
    const float* x   = (const float*)d_in[0];
    const int*   ei  = (const int*)  d_in[1];
    const float* W1  = (const float*)d_in[2];
    const float* a1s = (const float*)d_in[3];
    const float* a1d = (const float*)d_in[4];
    const float* b1  = (const float*)d_in[5];
    const float* W2  = (const float*)d_in[6];
    const float* a2s = (const float*)d_in[7];
    const float* a2d = (const float*)d_in[8];
    const float* b2  = (const float*)d_in[9];
    float* out = (float*)d_out;

    k_zero<<<(NN + 255) / 256, 256>>>();
    k_deg<<<(ET + 255) / 256, 256>>>(ei);
    k_scan1<<<49, 1024>>>();
    k_scan2<<<1, 32>>>();
    k_scan3<<<49, 1024>>>();
    k_fill<<<(ET + 255) / 256, 256>>>(ei);

    dim3 g1((NN + 127) / 128, F1 / 128);
    k_gemm1<<<g1, 256>>>(x, W1);
    k_al1<<<NN / 8, 256>>>(a1s, a1d);
    k_agg1<<<NN / 8, 256>>>(b1);
    k_gemm2<<<NN / 16, 256>>>(W2, a2s, a2d);
    k_agg2<<<NN / 8, 256>>>(b2, out);
}

// round 4
// speedup vs baseline: 1.2148x; 1.2148x over previous
#include <cuda_runtime.h>
#include <cuda_bf16.h>

#define NN   50000
#define EE   400000
#define ET   (EE + NN)      // 450000 edges incl self-loops
#define DIN  128
#define H1N  8
#define C1N  64
#define F1   512            // H1N*C1N
#define C2N  16

typedef unsigned long long ull;

// ------------------------- scratch (static device memory) -------------------
__device__ float g_h1[(size_t)NN * F1];     // layer-1 transformed features
__device__ float g_out1[(size_t)NN * F1];   // elu(layer-1 output)
__device__ float g_h2[(size_t)NN * C2N];    // layer-2 transformed features
__device__ float g_al1s[NN * H1N];
__device__ float g_al1d[NN * H1N];
__device__ float g_al2s[NN];
__device__ float g_al2d[NN];
__device__ float g_ew[(size_t)ET * H1N];    // per-edge unnormalized exp weights (permuted)
__device__ float g_rs[NN * H1N];            // per-node reciprocal denominators (permuted)
__device__ int   g_deg[NN];
__device__ int   g_cur[NN];
__device__ int   g_off[NN + 1];
__device__ int   g_bsums[64];
__device__ int   g_esrc[ET];

// ------------------------- small helpers ------------------------------------
__device__ __forceinline__ ull pack2(float lo, float hi) {
    ull r; asm("mov.b64 %0,{%1,%2};" : "=l"(r) : "f"(lo), "f"(hi)); return r;
}
__device__ __forceinline__ void unpack2(ull v, float& lo, float& hi) {
    asm("mov.b64 {%0,%1},%2;" : "=f"(lo), "=f"(hi) : "l"(v));
}
__device__ __forceinline__ ull fma2(ull a, ull b, ull c) {
    ull d; asm("fma.rn.f32x2 %0,%1,%2,%3;" : "=l"(d) : "l"(a), "l"(b), "l"(c)); return d;
}
__device__ __forceinline__ float lrelu(float x) { return x > 0.f ? x : 0.2f * x; }
__device__ __forceinline__ float eluf(float x)  { return x > 0.f ? x : (__expf(x) - 1.f); }

// ------------------------- CSR construction ---------------------------------
__global__ void k_zero() {
    int i = blockIdx.x * blockDim.x + threadIdx.x;
    if (i < NN) g_deg[i] = 0;
}

__global__ void k_deg(const int* __restrict__ ei) {
    int e = blockIdx.x * blockDim.x + threadIdx.x;
    if (e >= ET) return;
    int d = (e < EE) ? ei[EE + e] : (e - EE);
    atomicAdd(&g_deg[d], 1);
}

__global__ void k_scan1() {
    __shared__ int sh[1024];
    int i = blockIdx.x * 1024 + threadIdx.x;
    int v = (i < NN) ? g_deg[i] : 0;
    sh[threadIdx.x] = v;
    __syncthreads();
    #pragma unroll
    for (int ofs = 1; ofs < 1024; ofs <<= 1) {
        int t = 0;
        if ((int)threadIdx.x >= ofs) t = sh[threadIdx.x - ofs];
        __syncthreads();
        sh[threadIdx.x] += t;
        __syncthreads();
    }
    if (i < NN) g_off[i] = sh[threadIdx.x] - v;        // exclusive within block
    if (threadIdx.x == 1023) g_bsums[blockIdx.x] = sh[1023];
}

__global__ void k_scan2() {
    __shared__ int sh[64];
    int t = threadIdx.x;
    int v = (t < 49) ? g_bsums[t] : 0;
    sh[t] = v;
    __syncthreads();
    #pragma unroll
    for (int ofs = 1; ofs < 64; ofs <<= 1) {
        int u = 0;
        if (t >= ofs) u = sh[t - ofs];
        __syncthreads();
        sh[t] += u;
        __syncthreads();
    }
    if (t < 49) g_bsums[t] = sh[t] - v;   // exclusive
}

__global__ void k_scan3() {
    int i = blockIdx.x * 1024 + threadIdx.x;
    if (i < NN) {
        int o = g_off[i] + g_bsums[blockIdx.x];
        g_off[i] = o;
        g_cur[i] = o;
    }
    if (i == 0) g_off[NN] = ET;
}

__global__ void k_fill(const int* __restrict__ ei) {
    int e = blockIdx.x * blockDim.x + threadIdx.x;
    if (e >= ET) return;
    int s = (e < EE) ? ei[e] : (e - EE);
    int d = (e < EE) ? ei[EE + e] : (e - EE);
    int p = atomicAdd(&g_cur[d], 1);
    g_esrc[p] = s;
}

// ------------------------- GEMM1: h1 = x @ W1  (N x 128 x 512) --------------
// 128x128 tile, BK=16, 256 threads, 8x8 microtile, packed f32x2 FMAs.
// Epilogue also produces the per-node attention halves for the 2 heads this
// column tile covers (c-tile of 128 cols == 2 complete heads).
__global__ __launch_bounds__(256, 2) void k_gemm1(const float* __restrict__ x,
                                                  const float* __restrict__ w,
                                                  const float* __restrict__ a1s,
                                                  const float* __restrict__ a1d) {
    __shared__ __align__(16) float As[16][132];  // [k][row], padded
    __shared__ __align__(16) float Bs[16][128];  // [k][col]
    int tid = threadIdx.x;
    int lane = tid & 31;
    int r0 = blockIdx.x * 128, c0 = blockIdx.y * 128;
    int tx = tid & 15, ty = tid >> 4;

    ull acc[8][4];
    #pragma unroll
    for (int i = 0; i < 8; i++)
        #pragma unroll
        for (int j = 0; j < 4; j++) acc[i][j] = 0ULL;

    int arow = tid >> 2;   // 0..63
    int aq   = tid & 3;    // which float4 within the 16-wide k chunk
    int bk   = tid >> 5;   // 0..7
    int bq   = tid & 31;   // col quad

    for (int kb = 0; kb < 8; kb++) {
        int k0 = kb * 16;
        #pragma unroll
        for (int l = 0; l < 2; l++) {
            int row = arow + l * 64;
            int gr  = r0 + row;
            float4 v = make_float4(0.f, 0.f, 0.f, 0.f);
            if (gr < NN) v = *(const float4*)&x[(size_t)gr * DIN + k0 + aq * 4];
            As[aq * 4 + 0][row] = v.x;
            As[aq * 4 + 1][row] = v.y;
            As[aq * 4 + 2][row] = v.z;
            As[aq * 4 + 3][row] = v.w;
        }
        #pragma unroll
        for (int l = 0; l < 2; l++) {
            int k = bk + l * 8;
            float4 v = *(const float4*)&w[(size_t)(k0 + k) * F1 + c0 + bq * 4];
            *(float4*)&Bs[k][bq * 4] = v;
        }
        __syncthreads();
        #pragma unroll
        for (int kk = 0; kk < 16; kk++) {
            float4 a0 = *(float4*)&As[kk][ty * 8];
            float4 a1 = *(float4*)&As[kk][ty * 8 + 4];
            float4 b0 = *(float4*)&Bs[kk][tx * 8];
            float4 b1 = *(float4*)&Bs[kk][tx * 8 + 4];
            ull bp[4] = { pack2(b0.x, b0.y), pack2(b0.z, b0.w),
                          pack2(b1.x, b1.y), pack2(b1.z, b1.w) };
            float av[8] = { a0.x, a0.y, a0.z, a0.w, a1.x, a1.y, a1.z, a1.w };
            #pragma unroll
            for (int i = 0; i < 8; i++) {
                ull ap = pack2(av[i], av[i]);
                #pragma unroll
                for (int j = 0; j < 4; j++) acc[i][j] = fma2(ap, bp[j], acc[i][j]);
            }
        }
        __syncthreads();
    }

    // attention vector slices for this thread's 8 columns
    float asv[8], adv[8];
    #pragma unroll
    for (int j = 0; j < 8; j++) {
        asv[j] = a1s[c0 + tx * 8 + j];
        adv[j] = a1d[c0 + tx * 8 + j];
    }
    int h = (c0 >> 6) + ((lane >> 3) & 1);   // head written by this lane's 8-group

    #pragma unroll
    for (int i = 0; i < 8; i++) {
        int gr = r0 + ty * 8 + i;
        bool ok = (gr < NN);
        float o[8];
        #pragma unroll
        for (int j = 0; j < 4; j++) unpack2(acc[i][j], o[2 * j], o[2 * j + 1]);
        if (ok) {
            float* dst = &g_h1[(size_t)gr * F1 + c0 + tx * 8];
            *(float4*)dst       = make_float4(o[0], o[1], o[2], o[3]);
            *(float4*)(dst + 4) = make_float4(o[4], o[5], o[6], o[7]);
        }
        float ps = 0.f, pd = 0.f;
        #pragma unroll
        for (int j = 0; j < 8; j++) {
            ps = fmaf(o[j], asv[j], ps);
            pd = fmaf(o[j], adv[j], pd);
        }
        #pragma unroll
        for (int ofs = 4; ofs >= 1; ofs >>= 1) {   // reduce within 8-lane groups
            ps += __shfl_xor_sync(0xffffffffu, ps, ofs);
            pd += __shfl_xor_sync(0xffffffffu, pd, ofs);
        }
        if (ok && ((lane & 7) == 0)) {
            g_al1s[gr * 8 + h] = ps;
            g_al1d[gr * 8 + h] = pd;
        }
    }
}

// ------------------------- layer-1 pass A: edge weights + denominators ------
// warp per node. Stores unnormalized exp weights PERMUTED: position of head h
// is (h&1)*4 + (h>>1), so pass B reads one float4 per half-warp.
__global__ __launch_bounds__(256) void k_agg1a() {
    int tid = threadIdx.x;
    int wid = tid >> 5, lane = tid & 31;
    int n = blockIdx.x * 8 + wid;
    int beg = g_off[n], end = g_off[n + 1];

    float ad[8];
    {
        const float4* p = (const float4*)&g_al1d[n * 8];
        float4 u = p[0], v = p[1];
        ad[0]=u.x; ad[1]=u.y; ad[2]=u.z; ad[3]=u.w; ad[4]=v.x; ad[5]=v.y; ad[6]=v.z; ad[7]=v.w;
    }
    float sm[8];
    #pragma unroll
    for (int hh = 0; hh < 8; hh++) sm[hh] = 0.f;

    for (int e = beg + lane; e < end; e += 32) {
        int s = g_esrc[e];
        const float4* q = (const float4*)&g_al1s[s * 8];
        float4 u = q[0], v = q[1];
        float wv[8];
        wv[0] = __expf(lrelu(u.x + ad[0]));
        wv[1] = __expf(lrelu(u.y + ad[1]));
        wv[2] = __expf(lrelu(u.z + ad[2]));
        wv[3] = __expf(lrelu(u.w + ad[3]));
        wv[4] = __expf(lrelu(v.x + ad[4]));
        wv[5] = __expf(lrelu(v.y + ad[5]));
        wv[6] = __expf(lrelu(v.z + ad[6]));
        wv[7] = __expf(lrelu(v.w + ad[7]));
        #pragma unroll
        for (int hh = 0; hh < 8; hh++) sm[hh] += wv[hh];
        float4* o = (float4*)&g_ew[(size_t)e * 8];
        o[0] = make_float4(wv[0], wv[2], wv[4], wv[6]);   // even heads
        o[1] = make_float4(wv[1], wv[3], wv[5], wv[7]);   // odd heads
    }
    #pragma unroll
    for (int ofs = 16; ofs >= 1; ofs >>= 1)
        #pragma unroll
        for (int hh = 0; hh < 8; hh++) sm[hh] += __shfl_xor_sync(0xffffffffu, sm[hh], ofs);

    if (lane == 0) {
        float4* r = (float4*)&g_rs[n * 8];
        r[0] = make_float4(1.f / sm[0], 1.f / sm[2], 1.f / sm[4], 1.f / sm[6]);
        r[1] = make_float4(1.f / sm[1], 1.f / sm[3], 1.f / sm[5], 1.f / sm[7]);
    }
}

// ------------------------- layer-1 pass B: weighted gather + bias + ELU -----
__global__ __launch_bounds__(256) void k_agg1b(const float* __restrict__ b1) {
    __shared__ float sb1[F1];
    int tid = threadIdx.x;
    for (int i = tid; i < F1; i += 256) sb1[i] = b1[i];
    __syncthreads();
    int wid = tid >> 5, lane = tid & 31;
    int n = blockIdx.x * 8 + wid;
    int beg = g_off[n], end = g_off[n + 1];
    int hi = lane >> 4;

    float4 acc[4];
    #pragma unroll
    for (int j = 0; j < 4; j++) acc[j] = make_float4(0.f, 0.f, 0.f, 0.f);

    for (int e = beg; e < end; e++) {
        int s = g_esrc[e];
        float4 wv = *(const float4*)&g_ew[(size_t)e * 8 + hi * 4];  // w[2j+hi], j=0..3
        float wa[4] = { wv.x, wv.y, wv.z, wv.w };
        const float4* hp = (const float4*)&g_h1[(size_t)s * F1];
        #pragma unroll
        for (int j = 0; j < 4; j++) {
            float4 v = hp[lane + 32 * j];
            float a = wa[j];
            acc[j].x = fmaf(a, v.x, acc[j].x);
            acc[j].y = fmaf(a, v.y, acc[j].y);
            acc[j].z = fmaf(a, v.z, acc[j].z);
            acc[j].w = fmaf(a, v.w, acc[j].w);
        }
    }
    float4 rsv = *(const float4*)&g_rs[n * 8 + hi * 4];   // rs[2j+hi]
    float ra[4] = { rsv.x, rsv.y, rsv.z, rsv.w };

    float4* op = (float4*)&g_out1[(size_t)n * F1];
    #pragma unroll
    for (int j = 0; j < 4; j++) {
        int ch = lane * 4 + 128 * j;
        float4 bb = *(float4*)&sb1[ch];
        float4 o;
        o.x = eluf(acc[j].x * ra[j] + bb.x);
        o.y = eluf(acc[j].y * ra[j] + bb.y);
        o.z = eluf(acc[j].z * ra[j] + bb.z);
        o.w = eluf(acc[j].w * ra[j] + bb.w);
        op[lane + 32 * j] = o;
    }
}

// ------------------------- GEMM2 + layer-2 attention halves -----------------
// one warp handles 2 nodes; W2 staged in smem with pad-20 rows.
__global__ __launch_bounds__(256) void k_gemm2(const float* __restrict__ W2,
                                               const float* __restrict__ a2s,
                                               const float* __restrict__ a2d) {
    __shared__ __align__(16) float sw[F1 * 20];
    __shared__ float sa2s[16], sa2d[16];
    int tid = threadIdx.x;
    for (int i = tid; i < F1 * C2N; i += 256) {
        int k = i >> 4, o = i & 15;
        sw[k * 20 + o] = W2[i];
    }
    if (tid < 16) { sa2s[tid] = a2s[tid]; sa2d[tid] = a2d[tid]; }
    __syncthreads();
    int wid = tid >> 5, lane = tid & 31;
    int n0 = (blockIdx.x * 8 + wid) * 2;
    const float* vA = &g_out1[(size_t)n0 * F1];
    const float* vB = vA + F1;
    float4 pA[4], pB[4];
    #pragma unroll
    for (int q = 0; q < 4; q++) { pA[q] = make_float4(0,0,0,0); pB[q] = make_float4(0,0,0,0); }
    #pragma unroll
    for (int j = 0; j < 16; j++) {
        int k = lane + 32 * j;
        float a = vA[k], b = vB[k];
        const float4* wr = (const float4*)&sw[k * 20];
        #pragma unroll
        for (int q = 0; q < 4; q++) {
            float4 w = wr[q];
            pA[q].x = fmaf(a, w.x, pA[q].x); pA[q].y = fmaf(a, w.y, pA[q].y);
            pA[q].z = fmaf(a, w.z, pA[q].z); pA[q].w = fmaf(a, w.w, pA[q].w);
            pB[q].x = fmaf(b, w.x, pB[q].x); pB[q].y = fmaf(b, w.y, pB[q].y);
            pB[q].z = fmaf(b, w.z, pB[q].z); pB[q].w = fmaf(b, w.w, pB[q].w);
        }
    }
    #pragma unroll
    for (int o = 16; o >= 1; o >>= 1) {
        #pragma unroll
        for (int q = 0; q < 4; q++) {
            pA[q].x += __shfl_xor_sync(0xffffffffu, pA[q].x, o);
            pA[q].y += __shfl_xor_sync(0xffffffffu, pA[q].y, o);
            pA[q].z += __shfl_xor_sync(0xffffffffu, pA[q].z, o);
            pA[q].w += __shfl_xor_sync(0xffffffffu, pA[q].w, o);
            pB[q].x += __shfl_xor_sync(0xffffffffu, pB[q].x, o);
            pB[q].y += __shfl_xor_sync(0xffffffffu, pB[q].y, o);
            pB[q].z += __shfl_xor_sync(0xffffffffu, pB[q].z, o);
            pB[q].w += __shfl_xor_sync(0xffffffffu, pB[q].w, o);
        }
    }
    if (lane < 2) {
        int n = n0 + lane;
        float4 P[4];
        #pragma unroll
        for (int q = 0; q < 4; q++) P[q] = lane ? pB[q] : pA[q];
        float4* ho = (float4*)&g_h2[(size_t)n * C2N];
        #pragma unroll
        for (int q = 0; q < 4; q++) ho[q] = P[q];
        float ds = 0.f, dd = 0.f;
        #pragma unroll
        for (int q = 0; q < 4; q++) {
            ds += P[q].x * sa2s[q*4+0] + P[q].y * sa2s[q*4+1] + P[q].z * sa2s[q*4+2] + P[q].w * sa2s[q*4+3];
            dd += P[q].x * sa2d[q*4+0] + P[q].y * sa2d[q*4+1] + P[q].z * sa2d[q*4+2] + P[q].w * sa2d[q*4+3];
        }
        g_al2s[n] = ds;
        g_al2d[n] = dd;
    }
}

// ------------------------- layer-2 softmax + aggregation + bias -------------
__global__ __launch_bounds__(256) void k_agg2(const float* __restrict__ b2,
                                              float* __restrict__ out) {
    int tid = threadIdx.x;
    int wid = tid >> 5, lane = tid & 31;
    int n = blockIdx.x * 8 + wid;
    int beg = g_off[n], end = g_off[n + 1];
    float adn = g_al2d[n];

    float sm = 0.f;
    for (int e = beg + lane; e < end; e += 32) {
        int s = g_esrc[e];
        sm += __expf(lrelu(g_al2s[s] + adn));
    }
    #pragma unroll
    for (int o = 16; o >= 1; o >>= 1) sm += __shfl_xor_sync(0xffffffffu, sm, o);
    float rinv = 1.f / sm;

    int half = lane >> 4, hl = lane & 15;
    float acc = 0.f;
    for (int e2 = beg; e2 < end; e2 += 2) {
        int e = e2 + half;
        bool ok = (e < end);
        int s = 0;
        float av = 0.f;
        if (ok) s = g_esrc[e];
        if (ok && hl == 0) {
            float t = lrelu(g_al2s[s] + adn);
            av = __expf(t) * rinv;
        }
        av = __shfl_sync(0xffffffffu, av, half << 4);
        float v = ok ? g_h2[(size_t)s * C2N + hl] : 0.f;
        acc = fmaf(av, v, acc);
    }
    acc += __shfl_xor_sync(0xffffffffu, acc, 16);
    if (lane < 16) out[(size_t)n * C2N + lane] = acc + b2[lane];
}

// ------------------------- launch -------------------------------------------
extern "C" void kernel_launch(void* const* d_in, const int* in_sizes, int n_in,
                              void* d_out, int out_size) {
    const float* x   = (const float*)d_in[0];
    const int*   ei  = (const int*)  d_in[1];
    const float* W1  = (const float*)d_in[2];
    const float* a1s = (const float*)d_in[3];
    const float* a1d = (const float*)d_in[4];
    const float* b1  = (const float*)d_in[5];
    const float* W2  = (const float*)d_in[6];
    const float* a2s = (const float*)d_in[7];
    const float* a2d = (const float*)d_in[8];
    const float* b2  = (const float*)d_in[9];
    float* out = (float*)d_out;

    k_zero<<<(NN + 255) / 256, 256>>>();
    k_deg<<<(ET + 255) / 256, 256>>>(ei);
    k_scan1<<<49, 1024>>>();
    dim3 g1((NN + 127) / 128, F1 / 128);
    k_gemm1<<<g1, 256>>>(x, W1, a1s, a1d);   // launch index 3 -> profiled slot
    k_scan2<<<1, 64>>>();
    k_scan3<<<49, 1024>>>();
    k_fill<<<(ET + 255) / 256, 256>>>(ei);
    k_agg1a<<<NN / 8, 256>>>();
    k_agg1b<<<NN / 8, 256>>>(b1);
    k_gemm2<<<NN / 16, 256>>>(W2, a2s, a2d);
    k_agg2<<<NN / 8, 256>>>(b2, out);
}

// round 13
// speedup vs baseline: 1.3362x; 1.0999x over previous
#include <cuda_runtime.h>
#include <cuda_bf16.h>
#include <cstdint>

#define NN   50000
#define EE   400000
#define ET   (EE + NN)      // 450000 edges incl self-loops
#define DIN  128
#define H1N  8
#define C1N  64
#define F1   512            // H1N*C1N
#define C2N  16
#define XT   391            // ceil(NN/128) row tiles

typedef unsigned long long ull;

// ------------------------- scratch (static device memory) -------------------
__device__ float g_h1[(size_t)NN * F1];     // layer-1 transformed features
__device__ float g_out1[(size_t)NN * F1];   // elu(layer-1 output)
__device__ float g_h2[(size_t)NN * C2N];    // layer-2 transformed features
__device__ float g_al1s[NN * H1N];
__device__ float g_al1d[NN * H1N];
__device__ float g_al2s[NN];
__device__ float g_al2d[NN];
__device__ float g_ew[(size_t)ET * H1N];    // per-edge unnormalized exp weights (permuted)
__device__ float g_rs[NN * H1N];            // per-node reciprocal denominators (permuted)
__device__ int   g_deg[NN];
__device__ int   g_cur[NN];
__device__ int   g_off[NN + 1];
__device__ int   g_bsums[64];
__device__ int   g_esrc[ET];
// pre-swizzled bf16 hi/lo images for the mma.sync GEMM
__device__ __nv_bfloat16 g_xhi[(size_t)XT * 16384];
__device__ __nv_bfloat16 g_xlo[(size_t)XT * 16384];
__device__ __nv_bfloat16 g_whi[4 * 16384];
__device__ __nv_bfloat16 g_wlo[4 * 16384];

// ------------------------- small helpers ------------------------------------
__device__ __forceinline__ float lrelu(float x) { return x > 0.f ? x : 0.2f * x; }
__device__ __forceinline__ float eluf(float x)  { return x > 0.f ? x : (__expf(x) - 1.f); }

__device__ __forceinline__ uint32_t smem_u32(const void* p) {
    uint32_t a;
    asm("{ .reg .u64 t; cvta.to.shared.u64 t, %1; cvt.u32.u64 %0, t; }" : "=r"(a) : "l"(p));
    return a;
}

// XOR-swizzled byte offset within a 128x128 bf16 tile (row stride 256B,
// 16B chunk index XORed with row&7 -> conflict-free ldmatrix)
__device__ __forceinline__ uint32_t sw_off(int row, int k) {
    return (uint32_t)(row * 256 + (((k >> 3) ^ (row & 7)) << 4) + ((k & 7) << 1));
}

#define LDSM_X4(r0, r1, r2, r3, a) \
    asm volatile("ldmatrix.sync.aligned.m8n8.x4.shared.b16 {%0,%1,%2,%3}, [%4];" \
        : "=r"(r0), "=r"(r1), "=r"(r2), "=r"(r3) : "r"(a))

#define MMA_BF16(c, a, b0, b1) \
    asm volatile("mma.sync.aligned.m16n8k16.row.col.f32.bf16.bf16.f32 " \
        "{%0,%1,%2,%3}, {%4,%5,%6,%7}, {%8,%9}, {%0,%1,%2,%3};" \
        : "+f"((c)[0]), "+f"((c)[1]), "+f"((c)[2]), "+f"((c)[3]) \
        : "r"((a)[0]), "r"((a)[1]), "r"((a)[2]), "r"((a)[3]), "r"(b0), "r"(b1))

// ------------------------- CSR construction ---------------------------------
__global__ void k_zero() {
    int i = blockIdx.x * blockDim.x + threadIdx.x;
    if (i < NN) g_deg[i] = 0;
    if (i < NN * H1N) { g_al1s[i] = 0.f; g_al1d[i] = 0.f; }
}

__global__ void k_deg(const int* __restrict__ ei) {
    int e = blockIdx.x * blockDim.x + threadIdx.x;
    if (e >= ET) return;
    int d = (e < EE) ? ei[EE + e] : (e - EE);
    atomicAdd(&g_deg[d], 1);
}

__global__ void k_scan1() {
    __shared__ int sh[1024];
    int i = blockIdx.x * 1024 + threadIdx.x;
    int v = (i < NN) ? g_deg[i] : 0;
    sh[threadIdx.x] = v;
    __syncthreads();
    #pragma unroll
    for (int ofs = 1; ofs < 1024; ofs <<= 1) {
        int t = 0;
        if ((int)threadIdx.x >= ofs) t = sh[threadIdx.x - ofs];
        __syncthreads();
        sh[threadIdx.x] += t;
        __syncthreads();
    }
    if (i < NN) g_off[i] = sh[threadIdx.x] - v;
    if (threadIdx.x == 1023) g_bsums[blockIdx.x] = sh[1023];
}

__global__ void k_scan2() {
    __shared__ int sh[64];
    int t = threadIdx.x;
    int v = (t < 49) ? g_bsums[t] : 0;
    sh[t] = v;
    __syncthreads();
    #pragma unroll
    for (int ofs = 1; ofs < 64; ofs <<= 1) {
        int u = 0;
        if (t >= ofs) u = sh[t - ofs];
        __syncthreads();
        sh[t] += u;
        __syncthreads();
    }
    if (t < 49) g_bsums[t] = sh[t] - v;
}

__global__ void k_scan3() {
    int i = blockIdx.x * 1024 + threadIdx.x;
    if (i < NN) {
        int o = g_off[i] + g_bsums[blockIdx.x];
        g_off[i] = o;
        g_cur[i] = o;
    }
    if (i == 0) g_off[NN] = ET;
}

__global__ void k_fill(const int* __restrict__ ei) {
    int e = blockIdx.x * blockDim.x + threadIdx.x;
    if (e >= ET) return;
    int s = (e < EE) ? ei[e] : (e - EE);
    int d = (e < EE) ? ei[EE + e] : (e - EE);
    int p = atomicAdd(&g_cur[d], 1);
    g_esrc[p] = s;
}

// ------------------------- prep: x -> swizzled bf16 hi/lo tiles -------------
__global__ __launch_bounds__(256) void k_prep_x(const float* __restrict__ x) {
    int t = blockIdx.x;
    char* bh = (char*)g_xhi + (size_t)t * 32768;
    char* bl = (char*)g_xlo + (size_t)t * 32768;
    for (int g = threadIdx.x; g < 4096; g += 256) {
        int idx = g * 4;
        int row = idx >> 7, k = idx & 127;
        int gr = t * 128 + row;
        float4 v = make_float4(0.f, 0.f, 0.f, 0.f);
        if (gr < NN) v = *(const float4*)&x[(size_t)gr * DIN + k];
        __nv_bfloat16 hx = __float2bfloat16(v.x), hy = __float2bfloat16(v.y);
        __nv_bfloat16 hz = __float2bfloat16(v.z), hw = __float2bfloat16(v.w);
        __nv_bfloat162 h01 = __nv_bfloat162(hx, hy), h23 = __nv_bfloat162(hz, hw);
        __nv_bfloat162 l01 = __floats2bfloat162_rn(v.x - __bfloat162float(hx),
                                                   v.y - __bfloat162float(hy));
        __nv_bfloat162 l23 = __floats2bfloat162_rn(v.z - __bfloat162float(hz),
                                                   v.w - __bfloat162float(hw));
        uint32_t off = sw_off(row, k);
        uint2 hh; hh.x = *(uint32_t*)&h01; hh.y = *(uint32_t*)&h23;
        uint2 ll; ll.x = *(uint32_t*)&l01; ll.y = *(uint32_t*)&l23;
        *(uint2*)(bh + off) = hh;
        *(uint2*)(bl + off) = ll;
    }
}

// ------------------------- prep: W1 col-tiles -> transposed swizzled bf16 ---
// B tile layout: row = output col n (0..127 of this tile), col = k (0..127)
__global__ __launch_bounds__(256) void k_prep_w(const float* __restrict__ w) {
    int ct = blockIdx.x;                       // column tile 0..3
    char* bh = (char*)g_whi + (size_t)ct * 32768;
    char* bl = (char*)g_wlo + (size_t)ct * 32768;
    for (int g = threadIdx.x; g < 4096; g += 256) {
        int n = g >> 5, k4 = (g & 31) * 4;     // B row n, k4..k4+3
        float v[4];
        #pragma unroll
        for (int j = 0; j < 4; j++) v[j] = w[(size_t)(k4 + j) * F1 + ct * 128 + n];
        __nv_bfloat16 h0 = __float2bfloat16(v[0]), h1 = __float2bfloat16(v[1]);
        __nv_bfloat16 h2 = __float2bfloat16(v[2]), h3 = __float2bfloat16(v[3]);
        __nv_bfloat162 h01 = __nv_bfloat162(h0, h1), h23 = __nv_bfloat162(h2, h3);
        __nv_bfloat162 l01 = __floats2bfloat162_rn(v[0] - __bfloat162float(h0),
                                                   v[1] - __bfloat162float(h1));
        __nv_bfloat162 l23 = __floats2bfloat162_rn(v[2] - __bfloat162float(h2),
                                                   v[3] - __bfloat162float(h3));
        uint32_t off = sw_off(n, k4);
        uint2 hh; hh.x = *(uint32_t*)&h01; hh.y = *(uint32_t*)&h23;
        uint2 ll; ll.x = *(uint32_t*)&l01; ll.y = *(uint32_t*)&l23;
        *(uint2*)(bh + off) = hh;
        *(uint2*)(bl + off) = ll;
    }
}

// ------------------------- GEMM1 via mma.sync (split-bf16, 3 terms) ---------
// smem: sas@256(512B), sad@768(512B), tiles start at 1536 (NO overlap),
//       A_hi@1536, A_lo@34304, B_hi@67072, B_lo@99840  -> total 132608
#define G1_SMEM 132608
#define OFF_AH 1536
#define OFF_AL 34304
#define OFF_BH 67072
#define OFF_BL 99840

__global__ __launch_bounds__(256, 1) void k_gemm1_mma(const float* __restrict__ a1s,
                                                      const float* __restrict__ a1d) {
    extern __shared__ __align__(16) char smem[];
    uint32_t sb = smem_u32(smem);
    int tid = threadIdx.x;
    int bx = blockIdx.x, by = blockIdx.y;
    float* sas = (float*)(smem + 256);   // [128], bytes 256..767
    float* sad = (float*)(smem + 768);   // [128], bytes 768..1279

    if (tid < 128) { sas[tid] = a1s[by * 128 + tid]; sad[tid] = a1d[by * 128 + tid]; }

    // flat copies of pre-swizzled images into smem
    {
        const uint4* sAh = (const uint4*)((const char*)g_xhi + (size_t)bx * 32768);
        const uint4* sAl = (const uint4*)((const char*)g_xlo + (size_t)bx * 32768);
        const uint4* sBh = (const uint4*)((const char*)g_whi + (size_t)by * 32768);
        const uint4* sBl = (const uint4*)((const char*)g_wlo + (size_t)by * 32768);
        uint4* dAh = (uint4*)(smem + OFF_AH);
        uint4* dAl = (uint4*)(smem + OFF_AL);
        uint4* dBh = (uint4*)(smem + OFF_BH);
        uint4* dBl = (uint4*)(smem + OFF_BL);
        for (int i = tid; i < 2048; i += 256) {
            dAh[i] = sAh[i];
            dAl[i] = sAl[i];
            dBh[i] = sBh[i];
            dBl[i] = sBl[i];
        }
    }
    __syncthreads();

    int w = tid >> 5, lane = tid & 31;
    int wm = w >> 2, wn = w & 3;          // warp tile: rows wm*64, cols wn*32
    int gid = lane >> 2, tig = lane & 3;
    int l16 = lane & 15, lhi = lane >> 4; // ldmatrix addressing

    float acc[4][4][4];
    #pragma unroll
    for (int mi = 0; mi < 4; mi++)
        #pragma unroll
        for (int ni = 0; ni < 4; ni++)
            #pragma unroll
            for (int q = 0; q < 4; q++) acc[mi][ni][q] = 0.f;

    #pragma unroll
    for (int kb = 0; kb < 8; kb++) {
        int ch = kb * 2 + lhi;            // 16B chunk index for this lane
        uint32_t aH[4][4], aL[4][4], bH[2][4], bL[2][4];
        #pragma unroll
        for (int mi = 0; mi < 4; mi++) {
            int r = wm * 64 + mi * 16 + l16;
            uint32_t o = (uint32_t)(r * 256 + (((ch ^ (r & 7))) << 4));
            LDSM_X4(aH[mi][0], aH[mi][1], aH[mi][2], aH[mi][3], sb + OFF_AH + o);
            LDSM_X4(aL[mi][0], aL[mi][1], aL[mi][2], aL[mi][3], sb + OFF_AL + o);
        }
        #pragma unroll
        for (int nh = 0; nh < 2; nh++) {
            int r = wn * 32 + nh * 16 + l16;
            uint32_t o = (uint32_t)(r * 256 + (((ch ^ (r & 7))) << 4));
            LDSM_X4(bH[nh][0], bH[nh][1], bH[nh][2], bH[nh][3], sb + OFF_BH + o);
            LDSM_X4(bL[nh][0], bL[nh][1], bL[nh][2], bL[nh][3], sb + OFF_BL + o);
        }
        #pragma unroll
        for (int mi = 0; mi < 4; mi++) {
            #pragma unroll
            for (int nh = 0; nh < 2; nh++) {
                #pragma unroll
                for (int s = 0; s < 2; s++) {
                    int ni = nh * 2 + s;
                    MMA_BF16(acc[mi][ni], aH[mi], bH[nh][s], bH[nh][s + 2]);
                    MMA_BF16(acc[mi][ni], aH[mi], bL[nh][s], bL[nh][s + 2]);
                    MMA_BF16(acc[mi][ni], aL[mi], bH[nh][s], bH[nh][s + 2]);
                }
            }
        }
    }

    // epilogue: store h1 + fused attention partial sums
    int h = by * 2 + (wn >> 1);
    #pragma unroll
    for (int mi = 0; mi < 4; mi++) {
        int r0 = bx * 128 + wm * 64 + mi * 16 + gid;
        int r1 = r0 + 8;
        float ps0 = 0.f, pd0 = 0.f, ps1 = 0.f, pd1 = 0.f;
        #pragma unroll
        for (int ni = 0; ni < 4; ni++) {
            int c = wn * 32 + ni * 8 + tig * 2;
            float a0 = sas[c], a1 = sas[c + 1];
            float d0 = sad[c], d1 = sad[c + 1];
            float v0 = acc[mi][ni][0], v1 = acc[mi][ni][1];
            float v2 = acc[mi][ni][2], v3 = acc[mi][ni][3];
            ps0 += v0 * a0 + v1 * a1;  pd0 += v0 * d0 + v1 * d1;
            ps1 += v2 * a0 + v3 * a1;  pd1 += v2 * d0 + v3 * d1;
            if (r0 < NN) *(float2*)&g_h1[(size_t)r0 * F1 + by * 128 + c] = make_float2(v0, v1);
            if (r1 < NN) *(float2*)&g_h1[(size_t)r1 * F1 + by * 128 + c] = make_float2(v2, v3);
        }
        #pragma unroll
        for (int ofs = 1; ofs <= 2; ofs <<= 1) {
            ps0 += __shfl_xor_sync(0xffffffffu, ps0, ofs);
            pd0 += __shfl_xor_sync(0xffffffffu, pd0, ofs);
            ps1 += __shfl_xor_sync(0xffffffffu, ps1, ofs);
            pd1 += __shfl_xor_sync(0xffffffffu, pd1, ofs);
        }
        if (tig == 0) {
            if (r0 < NN) {
                atomicAdd(&g_al1s[r0 * 8 + h], ps0);
                atomicAdd(&g_al1d[r0 * 8 + h], pd0);
            }
            if (r1 < NN) {
                atomicAdd(&g_al1s[r1 * 8 + h], ps1);
                atomicAdd(&g_al1d[r1 * 8 + h], pd1);
            }
        }
    }
}

// ------------------------- layer-1 pass A: edge weights + denominators ------
__global__ __launch_bounds__(256) void k_agg1a() {
    int tid = threadIdx.x;
    int wid = tid >> 5, lane = tid & 31;
    int n = blockIdx.x * 8 + wid;
    int beg = g_off[n], end = g_off[n + 1];

    float ad[8];
    {
        const float4* p = (const float4*)&g_al1d[n * 8];
        float4 u = p[0], v = p[1];
        ad[0]=u.x; ad[1]=u.y; ad[2]=u.z; ad[3]=u.w; ad[4]=v.x; ad[5]=v.y; ad[6]=v.z; ad[7]=v.w;
    }
    float sm[8];
    #pragma unroll
    for (int hh = 0; hh < 8; hh++) sm[hh] = 0.f;

    for (int e = beg + lane; e < end; e += 32) {
        int s = g_esrc[e];
        const float4* q = (const float4*)&g_al1s[s * 8];
        float4 u = q[0], v = q[1];
        float wv[8];
        wv[0] = __expf(lrelu(u.x + ad[0]));
        wv[1] = __expf(lrelu(u.y + ad[1]));
        wv[2] = __expf(lrelu(u.z + ad[2]));
        wv[3] = __expf(lrelu(u.w + ad[3]));
        wv[4] = __expf(lrelu(v.x + ad[4]));
        wv[5] = __expf(lrelu(v.y + ad[5]));
        wv[6] = __expf(lrelu(v.z + ad[6]));
        wv[7] = __expf(lrelu(v.w + ad[7]));
        #pragma unroll
        for (int hh = 0; hh < 8; hh++) sm[hh] += wv[hh];
        float4* o = (float4*)&g_ew[(size_t)e * 8];
        o[0] = make_float4(wv[0], wv[2], wv[4], wv[6]);
        o[1] = make_float4(wv[1], wv[3], wv[5], wv[7]);
    }
    #pragma unroll
    for (int ofs = 16; ofs >= 1; ofs >>= 1)
        #pragma unroll
        for (int hh = 0; hh < 8; hh++) sm[hh] += __shfl_xor_sync(0xffffffffu, sm[hh], ofs);

    if (lane == 0) {
        float4* r = (float4*)&g_rs[n * 8];
        r[0] = make_float4(1.f / sm[0], 1.f / sm[2], 1.f / sm[4], 1.f / sm[6]);
        r[1] = make_float4(1.f / sm[1], 1.f / sm[3], 1.f / sm[5], 1.f / sm[7]);
    }
}

// ------------------------- layer-1 pass B: weighted gather + bias + ELU -----
__global__ __launch_bounds__(256) void k_agg1b(const float* __restrict__ b1) {
    __shared__ float sb1[F1];
    int tid = threadIdx.x;
    for (int i = tid; i < F1; i += 256) sb1[i] = b1[i];
    __syncthreads();
    int wid = tid >> 5, lane = tid & 31;
    int n = blockIdx.x * 8 + wid;
    int beg = g_off[n], end = g_off[n + 1];
    int hi = lane >> 4;

    float4 acc[4];
    #pragma unroll
    for (int j = 0; j < 4; j++) acc[j] = make_float4(0.f, 0.f, 0.f, 0.f);

    for (int e = beg; e < end; e++) {
        int s = g_esrc[e];
        float4 wv = *(const float4*)&g_ew[(size_t)e * 8 + hi * 4];
        float wa[4] = { wv.x, wv.y, wv.z, wv.w };
        const float4* hp = (const float4*)&g_h1[(size_t)s * F1];
        #pragma unroll
        for (int j = 0; j < 4; j++) {
            float4 v = hp[lane + 32 * j];
            float a = wa[j];
            acc[j].x = fmaf(a, v.x, acc[j].x);
            acc[j].y = fmaf(a, v.y, acc[j].y);
            acc[j].z = fmaf(a, v.z, acc[j].z);
            acc[j].w = fmaf(a, v.w, acc[j].w);
        }
    }
    float4 rsv = *(const float4*)&g_rs[n * 8 + hi * 4];
    float ra[4] = { rsv.x, rsv.y, rsv.z, rsv.w };

    float4* op = (float4*)&g_out1[(size_t)n * F1];
    #pragma unroll
    for (int j = 0; j < 4; j++) {
        int ch = lane * 4 + 128 * j;
        float4 bb = *(float4*)&sb1[ch];
        float4 o;
        o.x = eluf(acc[j].x * ra[j] + bb.x);
        o.y = eluf(acc[j].y * ra[j] + bb.y);
        o.z = eluf(acc[j].z * ra[j] + bb.z);
        o.w = eluf(acc[j].w * ra[j] + bb.w);
        op[lane + 32 * j] = o;
    }
}

// ------------------------- GEMM2 + layer-2 attention halves -----------------
__global__ __launch_bounds__(256) void k_gemm2(const float* __restrict__ W2,
                                               const float* __restrict__ a2s,
                                               const float* __restrict__ a2d) {
    __shared__ __align__(16) float sw[F1 * 20];
    __shared__ float sa2s[16], sa2d[16];
    int tid = threadIdx.x;
    for (int i = tid; i < F1 * C2N; i += 256) {
        int k = i >> 4, o = i & 15;
        sw[k * 20 + o] = W2[i];
    }
    if (tid < 16) { sa2s[tid] = a2s[tid]; sa2d[tid] = a2d[tid]; }
    __syncthreads();
    int wid = tid >> 5, lane = tid & 31;
    int n0 = (blockIdx.x * 8 + wid) * 2;
    const float* vA = &g_out1[(size_t)n0 * F1];
    const float* vB = vA + F1;
    float4 pA[4], pB[4];
    #pragma unroll
    for (int q = 0; q < 4; q++) { pA[q] = make_float4(0,0,0,0); pB[q] = make_float4(0,0,0,0); }
    #pragma unroll
    for (int j = 0; j < 16; j++) {
        int k = lane + 32 * j;
        float a = vA[k], b = vB[k];
        const float4* wr = (const float4*)&sw[k * 20];
        #pragma unroll
        for (int q = 0; q < 4; q++) {
            float4 w = wr[q];
            pA[q].x = fmaf(a, w.x, pA[q].x); pA[q].y = fmaf(a, w.y, pA[q].y);
            pA[q].z = fmaf(a, w.z, pA[q].z); pA[q].w = fmaf(a, w.w, pA[q].w);
            pB[q].x = fmaf(b, w.x, pB[q].x); pB[q].y = fmaf(b, w.y, pB[q].y);
            pB[q].z = fmaf(b, w.z, pB[q].z); pB[q].w = fmaf(b, w.w, pB[q].w);
        }
    }
    #pragma unroll
    for (int o = 16; o >= 1; o >>= 1) {
        #pragma unroll
        for (int q = 0; q < 4; q++) {
            pA[q].x += __shfl_xor_sync(0xffffffffu, pA[q].x, o);
            pA[q].y += __shfl_xor_sync(0xffffffffu, pA[q].y, o);
            pA[q].z += __shfl_xor_sync(0xffffffffu, pA[q].z, o);
            pA[q].w += __shfl_xor_sync(0xffffffffu, pA[q].w, o);
            pB[q].x += __shfl_xor_sync(0xffffffffu, pB[q].x, o);
            pB[q].y += __shfl_xor_sync(0xffffffffu, pB[q].y, o);
            pB[q].z += __shfl_xor_sync(0xffffffffu, pB[q].z, o);
            pB[q].w += __shfl_xor_sync(0xffffffffu, pB[q].w, o);
        }
    }
    if (lane < 2) {
        int n = n0 + lane;
        float4 P[4];
        #pragma unroll
        for (int q = 0; q < 4; q++) P[q] = lane ? pB[q] : pA[q];
        float4* ho = (float4*)&g_h2[(size_t)n * C2N];
        #pragma unroll
        for (int q = 0; q < 4; q++) ho[q] = P[q];
        float ds = 0.f, dd = 0.f;
        #pragma unroll
        for (int q = 0; q < 4; q++) {
            ds += P[q].x * sa2s[q*4+0] + P[q].y * sa2s[q*4+1] + P[q].z * sa2s[q*4+2] + P[q].w * sa2s[q*4+3];
            dd += P[q].x * sa2d[q*4+0] + P[q].y * sa2d[q*4+1] + P[q].z * sa2d[q*4+2] + P[q].w * sa2d[q*4+3];
        }
        g_al2s[n] = ds;
        g_al2d[n] = dd;
    }
}

// ------------------------- layer-2 softmax + aggregation + bias -------------
__global__ __launch_bounds__(256) void k_agg2(const float* __restrict__ b2,
                                              float* __restrict__ out) {
    int tid = threadIdx.x;
    int wid = tid >> 5, lane = tid & 31;
    int n = blockIdx.x * 8 + wid;
    int beg = g_off[n], end = g_off[n + 1];
    float adn = g_al2d[n];

    float sm = 0.f;
    for (int e = beg + lane; e < end; e += 32) {
        int s = g_esrc[e];
        sm += __expf(lrelu(g_al2s[s] + adn));
    }
    #pragma unroll
    for (int o = 16; o >= 1; o >>= 1) sm += __shfl_xor_sync(0xffffffffu, sm, o);
    float rinv = 1.f / sm;

    int half = lane >> 4, hl = lane & 15;
    float acc = 0.f;
    for (int e2 = beg; e2 < end; e2 += 2) {
        int e = e2 + half;
        bool ok = (e < end);
        int s = 0;
        float av = 0.f;
        if (ok) s = g_esrc[e];
        if (ok && hl == 0) {
            float t = lrelu(g_al2s[s] + adn);
            av = __expf(t) * rinv;
        }
        av = __shfl_sync(0xffffffffu, av, half << 4);
        float v = ok ? g_h2[(size_t)s * C2N + hl] : 0.f;
        acc = fmaf(av, v, acc);
    }
    acc += __shfl_xor_sync(0xffffffffu, acc, 16);
    if (lane < 16) out[(size_t)n * C2N + lane] = acc + b2[lane];
}

// ------------------------- launch -------------------------------------------
extern "C" void kernel_launch(void* const* d_in, const int* in_sizes, int n_in,
                              void* d_out, int out_size) {
    const float* x   = (const float*)d_in[0];
    const int*   ei  = (const int*)  d_in[1];
    const float* W1  = (const float*)d_in[2];
    const float* a1s = (const float*)d_in[3];
    const float* a1d = (const float*)d_in[4];
    const float* b1  = (const float*)d_in[5];
    const float* W2  = (const float*)d_in[6];
    const float* a2s = (const float*)d_in[7];
    const float* a2d = (const float*)d_in[8];
    const float* b2  = (const float*)d_in[9];
    float* out = (float*)d_out;

    cudaFuncSetAttribute(k_gemm1_mma, cudaFuncAttributeMaxDynamicSharedMemorySize, G1_SMEM);

    k_prep_x<<<XT, 256>>>(x);                       // 0
    k_prep_w<<<4, 256>>>(W1);                       // 1
    k_zero<<<(NN * H1N + 255) / 256, 256>>>();      // 2 (also zeroes al1s/al1d)
    k_gemm1_mma<<<dim3(XT, 4), 256, G1_SMEM>>>(a1s, a1d);  // 3 -> profiled slot
    k_deg<<<(ET + 255) / 256, 256>>>(ei);           // 4
    k_scan1<<<49, 1024>>>();                        // 5
    k_scan2<<<1, 64>>>();                           // 6
    k_scan3<<<49, 1024>>>();                        // 7
    k_fill<<<(ET + 255) / 256, 256>>>(ei);          // 8
    k_agg1a<<<NN / 8, 256>>>();                     // 9
    k_agg1b<<<NN / 8, 256>>>(b1);                   // 10
    k_gemm2<<<NN / 16, 256>>>(W2, a2s, a2d);        // 11
    k_agg2<<<NN / 8, 256>>>(b2, out);               // 12
}

// round 15
// speedup vs baseline: 1.5196x; 1.1372x over previous
#include <cuda_runtime.h>
#include <cuda_bf16.h>
#include <cstdint>

#define NN   50000
#define EE   400000
#define ET   (EE + NN)      // 450000 edges incl self-loops
#define DIN  128
#define H1N  8
#define C1N  64
#define F1   512            // H1N*C1N
#define C2N  16
#define XT   391            // ceil(NN/128) row tiles

typedef unsigned long long ull;

// ------------------------- scratch (static device memory) -------------------
__device__ float g_h1[(size_t)NN * F1];     // layer-1 transformed features
__device__ float g_out1[(size_t)NN * F1];   // elu(layer-1 output)
__device__ float g_h2[(size_t)NN * C2N];    // layer-2 transformed features
__device__ float g_al1s[NN * H1N];
__device__ float g_al1d[NN * H1N];
__device__ float g_al2s[NN];
__device__ float g_al2d[NN];
__device__ float g_ew[(size_t)ET * H1N];    // per-edge unnormalized exp weights (permuted)
__device__ float g_rs[NN * H1N];            // per-node reciprocal denominators (permuted)
__device__ int   g_deg[NN];
__device__ int   g_cur[NN];
__device__ int   g_off[NN + 1];
__device__ int   g_bsums[64];
__device__ int   g_esrc[ET];
// pre-swizzled bf16 hi/lo images for the mma.sync GEMM
__device__ __nv_bfloat16 g_xhi[(size_t)XT * 16384];
__device__ __nv_bfloat16 g_xlo[(size_t)XT * 16384];
__device__ __nv_bfloat16 g_whi[4 * 16384];
__device__ __nv_bfloat16 g_wlo[4 * 16384];

// ------------------------- small helpers ------------------------------------
__device__ __forceinline__ float lrelu(float x) { return x > 0.f ? x : 0.2f * x; }
__device__ __forceinline__ float eluf(float x)  { return x > 0.f ? x : (__expf(x) - 1.f); }

__device__ __forceinline__ uint32_t smem_u32(const void* p) {
    uint32_t a;
    asm("{ .reg .u64 t; cvta.to.shared.u64 t, %1; cvt.u32.u64 %0, t; }" : "=r"(a) : "l"(p));
    return a;
}

// XOR-swizzled byte offset within a 128xK bf16 tile (row stride 256B,
// 16B chunk index XORed with row&7 -> conflict-free ldmatrix)
__device__ __forceinline__ uint32_t sw_off(int row, int k) {
    return (uint32_t)(row * 256 + (((k >> 3) ^ (row & 7)) << 4) + ((k & 7) << 1));
}

#define LDSM_X4(r0, r1, r2, r3, a) \
    asm volatile("ldmatrix.sync.aligned.m8n8.x4.shared.b16 {%0,%1,%2,%3}, [%4];" \
        : "=r"(r0), "=r"(r1), "=r"(r2), "=r"(r3) : "r"(a))

#define MMA_BF16(c, a, b0, b1) \
    asm volatile("mma.sync.aligned.m16n8k16.row.col.f32.bf16.bf16.f32 " \
        "{%0,%1,%2,%3}, {%4,%5,%6,%7}, {%8,%9}, {%0,%1,%2,%3};" \
        : "+f"((c)[0]), "+f"((c)[1]), "+f"((c)[2]), "+f"((c)[3]) \
        : "r"((a)[0]), "r"((a)[1]), "r"((a)[2]), "r"((a)[3]), "r"(b0), "r"(b1))

#define CP_ASYNC16(dst, src) \
    asm volatile("cp.async.cg.shared.global [%0], [%1], 16;" :: "r"(dst), "l"(src))
#define CP_COMMIT_WAIT() \
    asm volatile("cp.async.commit_group;\ncp.async.wait_group 0;" ::: "memory")

// ------------------------- CSR construction ---------------------------------
__global__ void k_zero() {
    int i = blockIdx.x * blockDim.x + threadIdx.x;
    if (i < NN) g_deg[i] = 0;
    if (i < NN * H1N) { g_al1s[i] = 0.f; g_al1d[i] = 0.f; }
}

__global__ void k_deg(const int* __restrict__ ei) {
    int e = blockIdx.x * blockDim.x + threadIdx.x;
    if (e >= ET) return;
    int d = (e < EE) ? ei[EE + e] : (e - EE);
    atomicAdd(&g_deg[d], 1);
}

__global__ void k_scan1() {
    __shared__ int sh[1024];
    int i = blockIdx.x * 1024 + threadIdx.x;
    int v = (i < NN) ? g_deg[i] : 0;
    sh[threadIdx.x] = v;
    __syncthreads();
    #pragma unroll
    for (int ofs = 1; ofs < 1024; ofs <<= 1) {
        int t = 0;
        if ((int)threadIdx.x >= ofs) t = sh[threadIdx.x - ofs];
        __syncthreads();
        sh[threadIdx.x] += t;
        __syncthreads();
    }
    if (i < NN) g_off[i] = sh[threadIdx.x] - v;
    if (threadIdx.x == 1023) g_bsums[blockIdx.x] = sh[1023];
}

__global__ void k_scan2() {
    __shared__ int sh[64];
    int t = threadIdx.x;
    int v = (t < 49) ? g_bsums[t] : 0;
    sh[t] = v;
    __syncthreads();
    #pragma unroll
    for (int ofs = 1; ofs < 64; ofs <<= 1) {
        int u = 0;
        if (t >= ofs) u = sh[t - ofs];
        __syncthreads();
        sh[t] += u;
        __syncthreads();
    }
    if (t < 49) g_bsums[t] = sh[t] - v;
}

__global__ void k_scan3() {
    int i = blockIdx.x * 1024 + threadIdx.x;
    if (i < NN) {
        int o = g_off[i] + g_bsums[blockIdx.x];
        g_off[i] = o;
        g_cur[i] = o;
    }
    if (i == 0) g_off[NN] = ET;
}

__global__ void k_fill(const int* __restrict__ ei) {
    int e = blockIdx.x * blockDim.x + threadIdx.x;
    if (e >= ET) return;
    int s = (e < EE) ? ei[e] : (e - EE);
    int d = (e < EE) ? ei[EE + e] : (e - EE);
    int p = atomicAdd(&g_cur[d], 1);
    g_esrc[p] = s;
}

// ------------------------- prep: x -> swizzled bf16 hi/lo tiles -------------
__global__ __launch_bounds__(256) void k_prep_x(const float* __restrict__ x) {
    int t = blockIdx.x;
    char* bh = (char*)g_xhi + (size_t)t * 32768;
    char* bl = (char*)g_xlo + (size_t)t * 32768;
    for (int g = threadIdx.x; g < 4096; g += 256) {
        int idx = g * 4;
        int row = idx >> 7, k = idx & 127;
        int gr = t * 128 + row;
        float4 v = make_float4(0.f, 0.f, 0.f, 0.f);
        if (gr < NN) v = *(const float4*)&x[(size_t)gr * DIN + k];
        __nv_bfloat16 hx = __float2bfloat16(v.x), hy = __float2bfloat16(v.y);
        __nv_bfloat16 hz = __float2bfloat16(v.z), hw = __float2bfloat16(v.w);
        __nv_bfloat162 h01 = __nv_bfloat162(hx, hy), h23 = __nv_bfloat162(hz, hw);
        __nv_bfloat162 l01 = __floats2bfloat162_rn(v.x - __bfloat162float(hx),
                                                   v.y - __bfloat162float(hy));
        __nv_bfloat162 l23 = __floats2bfloat162_rn(v.z - __bfloat162float(hz),
                                                   v.w - __bfloat162float(hw));
        uint32_t off = sw_off(row, k);
        uint2 hh; hh.x = *(uint32_t*)&h01; hh.y = *(uint32_t*)&h23;
        uint2 ll; ll.x = *(uint32_t*)&l01; ll.y = *(uint32_t*)&l23;
        *(uint2*)(bh + off) = hh;
        *(uint2*)(bl + off) = ll;
    }
}

// ------------------------- prep: W1 col-tiles -> transposed swizzled bf16 ---
// B tile layout: row = output col n (0..127 of this tile), col = k (0..127)
__global__ __launch_bounds__(256) void k_prep_w(const float* __restrict__ w) {
    int ct = blockIdx.x;                       // column tile 0..3
    char* bh = (char*)g_whi + (size_t)ct * 32768;
    char* bl = (char*)g_wlo + (size_t)ct * 32768;
    for (int g = threadIdx.x; g < 4096; g += 256) {
        int n = g >> 5, k4 = (g & 31) * 4;     // B row n, k4..k4+3
        float v[4];
        #pragma unroll
        for (int j = 0; j < 4; j++) v[j] = w[(size_t)(k4 + j) * F1 + ct * 128 + n];
        __nv_bfloat16 h0 = __float2bfloat16(v[0]), h1 = __float2bfloat16(v[1]);
        __nv_bfloat16 h2 = __float2bfloat16(v[2]), h3 = __float2bfloat16(v[3]);
        __nv_bfloat162 h01 = __nv_bfloat162(h0, h1), h23 = __nv_bfloat162(h2, h3);
        __nv_bfloat162 l01 = __floats2bfloat162_rn(v[0] - __bfloat162float(h0),
                                                   v[1] - __bfloat162float(h1));
        __nv_bfloat162 l23 = __floats2bfloat162_rn(v[2] - __bfloat162float(h2),
                                                   v[3] - __bfloat162float(h3));
        uint32_t off = sw_off(n, k4);
        uint2 hh; hh.x = *(uint32_t*)&h01; hh.y = *(uint32_t*)&h23;
        uint2 ll; ll.x = *(uint32_t*)&l01; ll.y = *(uint32_t*)&l23;
        *(uint2*)(bh + off) = hh;
        *(uint2*)(bl + off) = ll;
    }
}

// ------------------------- GEMM1 via mma.sync (split-bf16, 3 terms) ---------
// CTA tile 128 rows x 64 cols (one head). smem: sas@0(256B), sad@256(256B),
// A_hi@512(32KB), A_lo@33280(32KB), B_hi@66048(16KB), B_lo@82432(16KB)
// total 98816 B -> 2 CTAs/SM.
#define G1_SMEM 98816
#define OFF_AH 512
#define OFF_AL 33280
#define OFF_BH 66048
#define OFF_BL 82432

__global__ __launch_bounds__(256, 2) void k_gemm1_mma(const float* __restrict__ a1s,
                                                      const float* __restrict__ a1d) {
    extern __shared__ __align__(16) char smem[];
    uint32_t sb = smem_u32(smem);
    int tid = threadIdx.x;
    int bx = blockIdx.x, by = blockIdx.y;     // by = head 0..7
    float* sas = (float*)(smem);       // [64]
    float* sad = (float*)(smem + 256); // [64]

    if (tid < 64) { sas[tid] = a1s[by * 64 + tid]; sad[tid] = a1d[by * 64 + tid]; }

    // async staging of pre-swizzled images
    {
        const char* srcAh = (const char*)g_xhi + (size_t)bx * 32768;
        const char* srcAl = (const char*)g_xlo + (size_t)bx * 32768;
        const char* srcBh = (const char*)g_whi + (size_t)(by >> 1) * 32768 + (size_t)(by & 1) * 16384;
        const char* srcBl = (const char*)g_wlo + (size_t)(by >> 1) * 32768 + (size_t)(by & 1) * 16384;
        #pragma unroll
        for (int i = 0; i < 8; i++) {        // A: 2048 x 16B each (hi, lo)
            int ofs = (tid + i * 256) * 16;
            CP_ASYNC16(sb + OFF_AH + ofs, srcAh + ofs);
            CP_ASYNC16(sb + OFF_AL + ofs, srcAl + ofs);
        }
        #pragma unroll
        for (int i = 0; i < 4; i++) {        // B: 1024 x 16B each (hi, lo)
            int ofs = (tid + i * 256) * 16;
            CP_ASYNC16(sb + OFF_BH + ofs, srcBh + ofs);
            CP_ASYNC16(sb + OFF_BL + ofs, srcBl + ofs);
        }
        CP_COMMIT_WAIT();
    }
    __syncthreads();

    int w = tid >> 5, lane = tid & 31;
    int wm = w >> 1, wn = w & 1;          // warp tile: rows wm*32, cols wn*32
    int gid = lane >> 2, tig = lane & 3;
    int l16 = lane & 15, lhi = lane >> 4; // ldmatrix addressing

    float acc[2][4][4];
    #pragma unroll
    for (int mi = 0; mi < 2; mi++)
        #pragma unroll
        for (int ni = 0; ni < 4; ni++)
            #pragma unroll
            for (int q = 0; q < 4; q++) acc[mi][ni][q] = 0.f;

    #pragma unroll
    for (int kb = 0; kb < 8; kb++) {
        int ch = kb * 2 + lhi;            // 16B chunk index for this lane
        uint32_t aH[2][4], aL[2][4], bH[2][4], bL[2][4];
        #pragma unroll
        for (int mi = 0; mi < 2; mi++) {
            int r = wm * 32 + mi * 16 + l16;
            uint32_t o = (uint32_t)(r * 256 + (((ch ^ (r & 7))) << 4));
            LDSM_X4(aH[mi][0], aH[mi][1], aH[mi][2], aH[mi][3], sb + OFF_AH + o);
            LDSM_X4(aL[mi][0], aL[mi][1], aL[mi][2], aL[mi][3], sb + OFF_AL + o);
        }
        #pragma unroll
        for (int nh = 0; nh < 2; nh++) {
            int r = wn * 32 + nh * 16 + l16;
            uint32_t o = (uint32_t)(r * 256 + (((ch ^ (r & 7))) << 4));
            LDSM_X4(bH[nh][0], bH[nh][1], bH[nh][2], bH[nh][3], sb + OFF_BH + o);
            LDSM_X4(bL[nh][0], bL[nh][1], bL[nh][2], bL[nh][3], sb + OFF_BL + o);
        }
        #pragma unroll
        for (int mi = 0; mi < 2; mi++) {
            #pragma unroll
            for (int nh = 0; nh < 2; nh++) {
                #pragma unroll
                for (int s = 0; s < 2; s++) {
                    int ni = nh * 2 + s;
                    MMA_BF16(acc[mi][ni], aH[mi], bH[nh][s], bH[nh][s + 2]);
                    MMA_BF16(acc[mi][ni], aH[mi], bL[nh][s], bL[nh][s + 2]);
                    MMA_BF16(acc[mi][ni], aL[mi], bH[nh][s], bH[nh][s + 2]);
                }
            }
        }
    }

    // epilogue: store h1 + fused attention partial sums (head = by)
    #pragma unroll
    for (int mi = 0; mi < 2; mi++) {
        int r0 = bx * 128 + wm * 32 + mi * 16 + gid;
        int r1 = r0 + 8;
        float ps0 = 0.f, pd0 = 0.f, ps1 = 0.f, pd1 = 0.f;
        #pragma unroll
        for (int ni = 0; ni < 4; ni++) {
            int c = wn * 32 + ni * 8 + tig * 2;
            float a0 = sas[c], a1 = sas[c + 1];
            float d0 = sad[c], d1 = sad[c + 1];
            float v0 = acc[mi][ni][0], v1 = acc[mi][ni][1];
            float v2 = acc[mi][ni][2], v3 = acc[mi][ni][3];
            ps0 += v0 * a0 + v1 * a1;  pd0 += v0 * d0 + v1 * d1;
            ps1 += v2 * a0 + v3 * a1;  pd1 += v2 * d0 + v3 * d1;
            if (r0 < NN) *(float2*)&g_h1[(size_t)r0 * F1 + by * 64 + c] = make_float2(v0, v1);
            if (r1 < NN) *(float2*)&g_h1[(size_t)r1 * F1 + by * 64 + c] = make_float2(v2, v3);
        }
        #pragma unroll
        for (int ofs = 1; ofs <= 2; ofs <<= 1) {
            ps0 += __shfl_xor_sync(0xffffffffu, ps0, ofs);
            pd0 += __shfl_xor_sync(0xffffffffu, pd0, ofs);
            ps1 += __shfl_xor_sync(0xffffffffu, ps1, ofs);
            pd1 += __shfl_xor_sync(0xffffffffu, pd1, ofs);
        }
        if (tig == 0) {
            if (r0 < NN) {
                atomicAdd(&g_al1s[r0 * 8 + by], ps0);
                atomicAdd(&g_al1d[r0 * 8 + by], pd0);
            }
            if (r1 < NN) {
                atomicAdd(&g_al1s[r1 * 8 + by], ps1);
                atomicAdd(&g_al1d[r1 * 8 + by], pd1);
            }
        }
    }
}

// ------------------------- layer-1 pass A: edge weights + denominators ------
__global__ __launch_bounds__(256) void k_agg1a() {
    int tid = threadIdx.x;
    int wid = tid >> 5, lane = tid & 31;
    int n = blockIdx.x * 8 + wid;
    int beg = g_off[n], end = g_off[n + 1];

    float ad[8];
    {
        const float4* p = (const float4*)&g_al1d[n * 8];
        float4 u = p[0], v = p[1];
        ad[0]=u.x; ad[1]=u.y; ad[2]=u.z; ad[3]=u.w; ad[4]=v.x; ad[5]=v.y; ad[6]=v.z; ad[7]=v.w;
    }
    float sm[8];
    #pragma unroll
    for (int hh = 0; hh < 8; hh++) sm[hh] = 0.f;

    for (int e = beg + lane; e < end; e += 32) {
        int s = g_esrc[e];
        const float4* q = (const float4*)&g_al1s[s * 8];
        float4 u = q[0], v = q[1];
        float wv[8];
        wv[0] = __expf(lrelu(u.x + ad[0]));
        wv[1] = __expf(lrelu(u.y + ad[1]));
        wv[2] = __expf(lrelu(u.z + ad[2]));
        wv[3] = __expf(lrelu(u.w + ad[3]));
        wv[4] = __expf(lrelu(v.x + ad[4]));
        wv[5] = __expf(lrelu(v.y + ad[5]));
        wv[6] = __expf(lrelu(v.z + ad[6]));
        wv[7] = __expf(lrelu(v.w + ad[7]));
        #pragma unroll
        for (int hh = 0; hh < 8; hh++) sm[hh] += wv[hh];
        float4* o = (float4*)&g_ew[(size_t)e * 8];
        o[0] = make_float4(wv[0], wv[2], wv[4], wv[6]);
        o[1] = make_float4(wv[1], wv[3], wv[5], wv[7]);
    }
    #pragma unroll
    for (int ofs = 16; ofs >= 1; ofs >>= 1)
        #pragma unroll
        for (int hh = 0; hh < 8; hh++) sm[hh] += __shfl_xor_sync(0xffffffffu, sm[hh], ofs);

    if (lane == 0) {
        float4* r = (float4*)&g_rs[n * 8];
        r[0] = make_float4(1.f / sm[0], 1.f / sm[2], 1.f / sm[4], 1.f / sm[6]);
        r[1] = make_float4(1.f / sm[1], 1.f / sm[3], 1.f / sm[5], 1.f / sm[7]);
    }
}

// ------------------------- layer-1 pass B: weighted gather + bias + ELU -----
__global__ __launch_bounds__(256) void k_agg1b(const float* __restrict__ b1) {
    __shared__ float sb1[F1];
    int tid = threadIdx.x;
    for (int i = tid; i < F1; i += 256) sb1[i] = b1[i];
    __syncthreads();
    int wid = tid >> 5, lane = tid & 31;
    int n = blockIdx.x * 8 + wid;
    int beg = g_off[n], end = g_off[n + 1];
    int hi = lane >> 4;

    float4 acc[4];
    #pragma unroll
    for (int j = 0; j < 4; j++) acc[j] = make_float4(0.f, 0.f, 0.f, 0.f);

    for (int e = beg; e < end; e++) {
        int s = g_esrc[e];
        float4 wv = *(const float4*)&g_ew[(size_t)e * 8 + hi * 4];
        float wa[4] = { wv.x, wv.y, wv.z, wv.w };
        const float4* hp = (const float4*)&g_h1[(size_t)s * F1];
        #pragma unroll
        for (int j = 0; j < 4; j++) {
            float4 v = hp[lane + 32 * j];
            float a = wa[j];
            acc[j].x = fmaf(a, v.x, acc[j].x);
            acc[j].y = fmaf(a, v.y, acc[j].y);
            acc[j].z = fmaf(a, v.z, acc[j].z);
            acc[j].w = fmaf(a, v.w, acc[j].w);
        }
    }
    float4 rsv = *(const float4*)&g_rs[n * 8 + hi * 4];
    float ra[4] = { rsv.x, rsv.y, rsv.z, rsv.w };

    float4* op = (float4*)&g_out1[(size_t)n * F1];
    #pragma unroll
    for (int j = 0; j < 4; j++) {
        int ch = lane * 4 + 128 * j;
        float4 bb = *(float4*)&sb1[ch];
        float4 o;
        o.x = eluf(acc[j].x * ra[j] + bb.x);
        o.y = eluf(acc[j].y * ra[j] + bb.y);
        o.z = eluf(acc[j].z * ra[j] + bb.z);
        o.w = eluf(acc[j].w * ra[j] + bb.w);
        op[lane + 32 * j] = o;
    }
}

// ------------------------- GEMM2 + layer-2 attention halves -----------------
__global__ __launch_bounds__(256) void k_gemm2(const float* __restrict__ W2,
                                               const float* __restrict__ a2s,
                                               const float* __restrict__ a2d) {
    __shared__ __align__(16) float sw[F1 * 20];
    __shared__ float sa2s[16], sa2d[16];
    int tid = threadIdx.x;
    for (int i = tid; i < F1 * C2N; i += 256) {
        int k = i >> 4, o = i & 15;
        sw[k * 20 + o] = W2[i];
    }
    if (tid < 16) { sa2s[tid] = a2s[tid]; sa2d[tid] = a2d[tid]; }
    __syncthreads();
    int wid = tid >> 5, lane = tid & 31;
    int n0 = (blockIdx.x * 8 + wid) * 2;
    const float* vA = &g_out1[(size_t)n0 * F1];
    const float* vB = vA + F1;
    float4 pA[4], pB[4];
    #pragma unroll
    for (int q = 0; q < 4; q++) { pA[q] = make_float4(0,0,0,0); pB[q] = make_float4(0,0,0,0); }
    #pragma unroll
    for (int j = 0; j < 16; j++) {
        int k = lane + 32 * j;
        float a = vA[k], b = vB[k];
        const float4* wr = (const float4*)&sw[k * 20];
        #pragma unroll
        for (int q = 0; q < 4; q++) {
            float4 w = wr[q];
            pA[q].x = fmaf(a, w.x, pA[q].x); pA[q].y = fmaf(a, w.y, pA[q].y);
            pA[q].z = fmaf(a, w.z, pA[q].z); pA[q].w = fmaf(a, w.w, pA[q].w);
            pB[q].x = fmaf(b, w.x, pB[q].x); pB[q].y = fmaf(b, w.y, pB[q].y);
            pB[q].z = fmaf(b, w.z, pB[q].z); pB[q].w = fmaf(b, w.w, pB[q].w);
        }
    }
    #pragma unroll
    for (int o = 16; o >= 1; o >>= 1) {
        #pragma unroll
        for (int q = 0; q < 4; q++) {
            pA[q].x += __shfl_xor_sync(0xffffffffu, pA[q].x, o);
            pA[q].y += __shfl_xor_sync(0xffffffffu, pA[q].y, o);
            pA[q].z += __shfl_xor_sync(0xffffffffu, pA[q].z, o);
            pA[q].w += __shfl_xor_sync(0xffffffffu, pA[q].w, o);
            pB[q].x += __shfl_xor_sync(0xffffffffu, pB[q].x, o);
            pB[q].y += __shfl_xor_sync(0xffffffffu, pB[q].y, o);
            pB[q].z += __shfl_xor_sync(0xffffffffu, pB[q].z, o);
            pB[q].w += __shfl_xor_sync(0xffffffffu, pB[q].w, o);
        }
    }
    if (lane < 2) {
        int n = n0 + lane;
        float4 P[4];
        #pragma unroll
        for (int q = 0; q < 4; q++) P[q] = lane ? pB[q] : pA[q];
        float4* ho = (float4*)&g_h2[(size_t)n * C2N];
        #pragma unroll
        for (int q = 0; q < 4; q++) ho[q] = P[q];
        float ds = 0.f, dd = 0.f;
        #pragma unroll
        for (int q = 0; q < 4; q++) {
            ds += P[q].x * sa2s[q*4+0] + P[q].y * sa2s[q*4+1] + P[q].z * sa2s[q*4+2] + P[q].w * sa2s[q*4+3];
            dd += P[q].x * sa2d[q*4+0] + P[q].y * sa2d[q*4+1] + P[q].z * sa2d[q*4+2] + P[q].w * sa2d[q*4+3];
        }
        g_al2s[n] = ds;
        g_al2d[n] = dd;
    }
}

// ------------------------- layer-2 softmax + aggregation + bias -------------
__global__ __launch_bounds__(256) void k_agg2(const float* __restrict__ b2,
                                              float* __restrict__ out) {
    int tid = threadIdx.x;
    int wid = tid >> 5, lane = tid & 31;
    int n = blockIdx.x * 8 + wid;
    int beg = g_off[n], end = g_off[n + 1];
    float adn = g_al2d[n];

    float sm = 0.f;
    for (int e = beg + lane; e < end; e += 32) {
        int s = g_esrc[e];
        sm += __expf(lrelu(g_al2s[s] + adn));
    }
    #pragma unroll
    for (int o = 16; o >= 1; o >>= 1) sm += __shfl_xor_sync(0xffffffffu, sm, o);
    float rinv = 1.f / sm;

    int half = lane >> 4, hl = lane & 15;
    float acc = 0.f;
    for (int e2 = beg; e2 < end; e2 += 2) {
        int e = e2 + half;
        bool ok = (e < end);
        int s = 0;
        float av = 0.f;
        if (ok) s = g_esrc[e];
        if (ok && hl == 0) {
            float t = lrelu(g_al2s[s] + adn);
            av = __expf(t) * rinv;
        }
        av = __shfl_sync(0xffffffffu, av, half << 4);
        float v = ok ? g_h2[(size_t)s * C2N + hl] : 0.f;
        acc = fmaf(av, v, acc);
    }
    acc += __shfl_xor_sync(0xffffffffu, acc, 16);
    if (lane < 16) out[(size_t)n * C2N + lane] = acc + b2[lane];
}

// ------------------------- launch -------------------------------------------
extern "C" void kernel_launch(void* const* d_in, const int* in_sizes, int n_in,
                              void* d_out, int out_size) {
    const float* x   = (const float*)d_in[0];
    const int*   ei  = (const int*)  d_in[1];
    const float* W1  = (const float*)d_in[2];
    const float* a1s = (const float*)d_in[3];
    const float* a1d = (const float*)d_in[4];
    const float* b1  = (const float*)d_in[5];
    const float* W2  = (const float*)d_in[6];
    const float* a2s = (const float*)d_in[7];
    const float* a2d = (const float*)d_in[8];
    const float* b2  = (const float*)d_in[9];
    float* out = (float*)d_out;

    cudaFuncSetAttribute(k_gemm1_mma, cudaFuncAttributeMaxDynamicSharedMemorySize, G1_SMEM);

    k_prep_x<<<XT, 256>>>(x);                       // 0
    k_prep_w<<<4, 256>>>(W1);                       // 1
    k_zero<<<(NN * H1N + 255) / 256, 256>>>();      // 2 (also zeroes al1s/al1d)
    k_gemm1_mma<<<dim3(XT, 8), 256, G1_SMEM>>>(a1s, a1d);  // 3 -> profiled slot
    k_deg<<<(ET + 255) / 256, 256>>>(ei);           // 4
    k_scan1<<<49, 1024>>>();                        // 5
    k_scan2<<<1, 64>>>();                           // 6
    k_scan3<<<49, 1024>>>();                        // 7
    k_fill<<<(ET + 255) / 256, 256>>>(ei);          // 8
    k_agg1a<<<NN / 8, 256>>>();                     // 9
    k_agg1b<<<NN / 8, 256>>>(b1);                   // 10
    k_gemm2<<<NN / 16, 256>>>(W2, a2s, a2d);        // 11
    k_agg2<<<NN / 8, 256>>>(b2, out);               // 12
}

// round 17
// speedup vs baseline: 1.5863x; 1.0439x over previous
#include <cuda_runtime.h>
#include <cuda_bf16.h>
#include <cuda_fp16.h>
#include <cstdint>

#define NN   50000
#define EE   400000
#define ET   (EE + NN)      // 450000 edges incl self-loops
#define DIN  128
#define H1N  8
#define C1N  64
#define F1   512            // H1N*C1N
#define C2N  16
#define XT   391            // ceil(NN/128) row tiles

typedef unsigned long long ull;

// ------------------------- scratch (static device memory) -------------------
__device__ __half g_h1h[(size_t)NN * F1];   // layer-1 features (fp16, gather copy)
__device__ float g_out1[(size_t)NN * F1];   // elu(layer-1 output)
__device__ float g_h2[(size_t)NN * C2N];    // layer-2 transformed features
__device__ float g_al1s[NN * H1N];
__device__ float g_al1d[NN * H1N];
__device__ float g_al2s[NN];
__device__ float g_al2d[NN];
__device__ float g_ew[(size_t)ET * H1N];    // per-edge unnormalized exp weights (permuted)
__device__ float g_rs[NN * H1N];            // per-node reciprocal denominators (permuted)
__device__ int   g_deg[NN];
__device__ int   g_cur[NN];
__device__ int   g_off[NN + 1];
__device__ int   g_bsums[64];
__device__ int   g_esrc[ET];
// pre-swizzled bf16 hi/lo images for the mma.sync GEMM
__device__ __nv_bfloat16 g_xhi[(size_t)XT * 16384];
__device__ __nv_bfloat16 g_xlo[(size_t)XT * 16384];
__device__ __nv_bfloat16 g_whi[4 * 16384];
__device__ __nv_bfloat16 g_wlo[4 * 16384];

// ------------------------- small helpers ------------------------------------
__device__ __forceinline__ float lrelu(float x) { return x > 0.f ? x : 0.2f * x; }
__device__ __forceinline__ float eluf(float x)  { return x > 0.f ? x : (__expf(x) - 1.f); }

__device__ __forceinline__ uint32_t smem_u32(const void* p) {
    uint32_t a;
    asm("{ .reg .u64 t; cvta.to.shared.u64 t, %1; cvt.u32.u64 %0, t; }" : "=r"(a) : "l"(p));
    return a;
}

// XOR-swizzled byte offset within a 128xK bf16 tile (row stride 256B,
// 16B chunk index XORed with row&7 -> conflict-free ldmatrix)
__device__ __forceinline__ uint32_t sw_off(int row, int k) {
    return (uint32_t)(row * 256 + (((k >> 3) ^ (row & 7)) << 4) + ((k & 7) << 1));
}

#define LDSM_X4(r0, r1, r2, r3, a) \
    asm volatile("ldmatrix.sync.aligned.m8n8.x4.shared.b16 {%0,%1,%2,%3}, [%4];" \
        : "=r"(r0), "=r"(r1), "=r"(r2), "=r"(r3) : "r"(a))

#define MMA_BF16(c, a, b0, b1) \
    asm volatile("mma.sync.aligned.m16n8k16.row.col.f32.bf16.bf16.f32 " \
        "{%0,%1,%2,%3}, {%4,%5,%6,%7}, {%8,%9}, {%0,%1,%2,%3};" \
        : "+f"((c)[0]), "+f"((c)[1]), "+f"((c)[2]), "+f"((c)[3]) \
        : "r"((a)[0]), "r"((a)[1]), "r"((a)[2]), "r"((a)[3]), "r"(b0), "r"(b1))

#define CP_ASYNC16(dst, src) \
    asm volatile("cp.async.cg.shared.global [%0], [%1], 16;" :: "r"(dst), "l"(src))
#define CP_COMMIT_WAIT() \
    asm volatile("cp.async.commit_group;\ncp.async.wait_group 0;" ::: "memory")

// ------------------------- CSR construction ---------------------------------
__global__ void k_zero() {
    int i = blockIdx.x * blockDim.x + threadIdx.x;
    if (i < NN) g_deg[i] = 0;
    if (i < NN * H1N) { g_al1s[i] = 0.f; g_al1d[i] = 0.f; }
}

__global__ void k_deg(const int* __restrict__ ei) {
    int e = blockIdx.x * blockDim.x + threadIdx.x;
    if (e >= ET) return;
    int d = (e < EE) ? ei[EE + e] : (e - EE);
    atomicAdd(&g_deg[d], 1);
}

__global__ void k_scan1() {
    __shared__ int sh[1024];
    int i = blockIdx.x * 1024 + threadIdx.x;
    int v = (i < NN) ? g_deg[i] : 0;
    sh[threadIdx.x] = v;
    __syncthreads();
    #pragma unroll
    for (int ofs = 1; ofs < 1024; ofs <<= 1) {
        int t = 0;
        if ((int)threadIdx.x >= ofs) t = sh[threadIdx.x - ofs];
        __syncthreads();
        sh[threadIdx.x] += t;
        __syncthreads();
    }
    if (i < NN) g_off[i] = sh[threadIdx.x] - v;
    if (threadIdx.x == 1023) g_bsums[blockIdx.x] = sh[1023];
}

__global__ void k_scan2() {
    __shared__ int sh[64];
    int t = threadIdx.x;
    int v = (t < 49) ? g_bsums[t] : 0;
    sh[t] = v;
    __syncthreads();
    #pragma unroll
    for (int ofs = 1; ofs < 64; ofs <<= 1) {
        int u = 0;
        if (t >= ofs) u = sh[t - ofs];
        __syncthreads();
        sh[t] += u;
        __syncthreads();
    }
    if (t < 49) g_bsums[t] = sh[t] - v;
}

__global__ void k_scan3() {
    int i = blockIdx.x * 1024 + threadIdx.x;
    if (i < NN) {
        int o = g_off[i] + g_bsums[blockIdx.x];
        g_off[i] = o;
        g_cur[i] = o;
    }
    if (i == 0) g_off[NN] = ET;
}

__global__ void k_fill(const int* __restrict__ ei) {
    int e = blockIdx.x * blockDim.x + threadIdx.x;
    if (e >= ET) return;
    int s = (e < EE) ? ei[e] : (e - EE);
    int d = (e < EE) ? ei[EE + e] : (e - EE);
    int p = atomicAdd(&g_cur[d], 1);
    g_esrc[p] = s;
}

// ------------------------- prep: x -> swizzled bf16 hi/lo tiles -------------
__global__ __launch_bounds__(256) void k_prep_x(const float* __restrict__ x) {
    int t = blockIdx.x;
    char* bh = (char*)g_xhi + (size_t)t * 32768;
    char* bl = (char*)g_xlo + (size_t)t * 32768;
    for (int g = threadIdx.x; g < 4096; g += 256) {
        int idx = g * 4;
        int row = idx >> 7, k = idx & 127;
        int gr = t * 128 + row;
        float4 v = make_float4(0.f, 0.f, 0.f, 0.f);
        if (gr < NN) v = *(const float4*)&x[(size_t)gr * DIN + k];
        __nv_bfloat16 hx = __float2bfloat16(v.x), hy = __float2bfloat16(v.y);
        __nv_bfloat16 hz = __float2bfloat16(v.z), hw = __float2bfloat16(v.w);
        __nv_bfloat162 h01 = __nv_bfloat162(hx, hy), h23 = __nv_bfloat162(hz, hw);
        __nv_bfloat162 l01 = __floats2bfloat162_rn(v.x - __bfloat162float(hx),
                                                   v.y - __bfloat162float(hy));
        __nv_bfloat162 l23 = __floats2bfloat162_rn(v.z - __bfloat162float(hz),
                                                   v.w - __bfloat162float(hw));
        uint32_t off = sw_off(row, k);
        uint2 hh; hh.x = *(uint32_t*)&h01; hh.y = *(uint32_t*)&h23;
        uint2 ll; ll.x = *(uint32_t*)&l01; ll.y = *(uint32_t*)&l23;
        *(uint2*)(bh + off) = hh;
        *(uint2*)(bl + off) = ll;
    }
}

// ------------------------- prep: W1 col-tiles -> transposed swizzled bf16 ---
// B tile layout: row = output col n (0..127 of this tile), col = k (0..127)
__global__ __launch_bounds__(256) void k_prep_w(const float* __restrict__ w) {
    int ct = blockIdx.x;                       // column tile 0..3
    char* bh = (char*)g_whi + (size_t)ct * 32768;
    char* bl = (char*)g_wlo + (size_t)ct * 32768;
    for (int g = threadIdx.x; g < 4096; g += 256) {
        int n = g >> 5, k4 = (g & 31) * 4;     // B row n, k4..k4+3
        float v[4];
        #pragma unroll
        for (int j = 0; j < 4; j++) v[j] = w[(size_t)(k4 + j) * F1 + ct * 128 + n];
        __nv_bfloat16 h0 = __float2bfloat16(v[0]), h1 = __float2bfloat16(v[1]);
        __nv_bfloat16 h2 = __float2bfloat16(v[2]), h3 = __float2bfloat16(v[3]);
        __nv_bfloat162 h01 = __nv_bfloat162(h0, h1), h23 = __nv_bfloat162(h2, h3);
        __nv_bfloat162 l01 = __floats2bfloat162_rn(v[0] - __bfloat162float(h0),
                                                   v[1] - __bfloat162float(h1));
        __nv_bfloat162 l23 = __floats2bfloat162_rn(v[2] - __bfloat162float(h2),
                                                   v[3] - __bfloat162float(h3));
        uint32_t off = sw_off(n, k4);
        uint2 hh; hh.x = *(uint32_t*)&h01; hh.y = *(uint32_t*)&h23;
        uint2 ll; ll.x = *(uint32_t*)&l01; ll.y = *(uint32_t*)&l23;
        *(uint2*)(bh + off) = hh;
        *(uint2*)(bl + off) = ll;
    }
}

// ------------------------- GEMM1 via mma.sync (split-bf16, 3 terms) ---------
// CTA tile 128 rows x 64 cols (one head). smem: sas@0(256B), sad@256(256B),
// A_hi@512(32KB), A_lo@33280(32KB), B_hi@66048(16KB), B_lo@82432(16KB)
// total 98816 B -> 2 CTAs/SM.
#define G1_SMEM 98816
#define OFF_AH 512
#define OFF_AL 33280
#define OFF_BH 66048
#define OFF_BL 82432

__global__ __launch_bounds__(256, 2) void k_gemm1_mma(const float* __restrict__ a1s,
                                                      const float* __restrict__ a1d) {
    extern __shared__ __align__(16) char smem[];
    uint32_t sb = smem_u32(smem);
    int tid = threadIdx.x;
    int bx = blockIdx.x, by = blockIdx.y;     // by = head 0..7
    float* sas = (float*)(smem);       // [64]
    float* sad = (float*)(smem + 256); // [64]

    if (tid < 64) { sas[tid] = a1s[by * 64 + tid]; sad[tid] = a1d[by * 64 + tid]; }

    // async staging of pre-swizzled images
    {
        const char* srcAh = (const char*)g_xhi + (size_t)bx * 32768;
        const char* srcAl = (const char*)g_xlo + (size_t)bx * 32768;
        const char* srcBh = (const char*)g_whi + (size_t)(by >> 1) * 32768 + (size_t)(by & 1) * 16384;
        const char* srcBl = (const char*)g_wlo + (size_t)(by >> 1) * 32768 + (size_t)(by & 1) * 16384;
        #pragma unroll
        for (int i = 0; i < 8; i++) {        // A: 2048 x 16B each (hi, lo)
            int ofs = (tid + i * 256) * 16;
            CP_ASYNC16(sb + OFF_AH + ofs, srcAh + ofs);
            CP_ASYNC16(sb + OFF_AL + ofs, srcAl + ofs);
        }
        #pragma unroll
        for (int i = 0; i < 4; i++) {        // B: 1024 x 16B each (hi, lo)
            int ofs = (tid + i * 256) * 16;
            CP_ASYNC16(sb + OFF_BH + ofs, srcBh + ofs);
            CP_ASYNC16(sb + OFF_BL + ofs, srcBl + ofs);
        }
        CP_COMMIT_WAIT();
    }
    __syncthreads();

    int w = tid >> 5, lane = tid & 31;
    int wm = w >> 1, wn = w & 1;          // warp tile: rows wm*32, cols wn*32
    int gid = lane >> 2, tig = lane & 3;
    int l16 = lane & 15, lhi = lane >> 4; // ldmatrix addressing

    float acc[2][4][4];
    #pragma unroll
    for (int mi = 0; mi < 2; mi++)
        #pragma unroll
        for (int ni = 0; ni < 4; ni++)
            #pragma unroll
            for (int q = 0; q < 4; q++) acc[mi][ni][q] = 0.f;

    #pragma unroll
    for (int kb = 0; kb < 8; kb++) {
        int ch = kb * 2 + lhi;            // 16B chunk index for this lane
        uint32_t aH[2][4], aL[2][4], bH[2][4], bL[2][4];
        #pragma unroll
        for (int mi = 0; mi < 2; mi++) {
            int r = wm * 32 + mi * 16 + l16;
            uint32_t o = (uint32_t)(r * 256 + (((ch ^ (r & 7))) << 4));
            LDSM_X4(aH[mi][0], aH[mi][1], aH[mi][2], aH[mi][3], sb + OFF_AH + o);
            LDSM_X4(aL[mi][0], aL[mi][1], aL[mi][2], aL[mi][3], sb + OFF_AL + o);
        }
        #pragma unroll
        for (int nh = 0; nh < 2; nh++) {
            int r = wn * 32 + nh * 16 + l16;
            uint32_t o = (uint32_t)(r * 256 + (((ch ^ (r & 7))) << 4));
            LDSM_X4(bH[nh][0], bH[nh][1], bH[nh][2], bH[nh][3], sb + OFF_BH + o);
            LDSM_X4(bL[nh][0], bL[nh][1], bL[nh][2], bL[nh][3], sb + OFF_BL + o);
        }
        #pragma unroll
        for (int mi = 0; mi < 2; mi++) {
            #pragma unroll
            for (int nh = 0; nh < 2; nh++) {
                #pragma unroll
                for (int s = 0; s < 2; s++) {
                    int ni = nh * 2 + s;
                    MMA_BF16(acc[mi][ni], aH[mi], bH[nh][s], bH[nh][s + 2]);
                    MMA_BF16(acc[mi][ni], aH[mi], bL[nh][s], bL[nh][s + 2]);
                    MMA_BF16(acc[mi][ni], aL[mi], bH[nh][s], bH[nh][s + 2]);
                }
            }
        }
    }

    // epilogue: store h1 (fp16) + fused attention partial sums (head = by)
    #pragma unroll
    for (int mi = 0; mi < 2; mi++) {
        int r0 = bx * 128 + wm * 32 + mi * 16 + gid;
        int r1 = r0 + 8;
        float ps0 = 0.f, pd0 = 0.f, ps1 = 0.f, pd1 = 0.f;
        #pragma unroll
        for (int ni = 0; ni < 4; ni++) {
            int c = wn * 32 + ni * 8 + tig * 2;
            float a0 = sas[c], a1 = sas[c + 1];
            float d0 = sad[c], d1 = sad[c + 1];
            float v0 = acc[mi][ni][0], v1 = acc[mi][ni][1];
            float v2 = acc[mi][ni][2], v3 = acc[mi][ni][3];
            ps0 += v0 * a0 + v1 * a1;  pd0 += v0 * d0 + v1 * d1;
            ps1 += v2 * a0 + v3 * a1;  pd1 += v2 * d0 + v3 * d1;
            if (r0 < NN) *(__half2*)&g_h1h[(size_t)r0 * F1 + by * 64 + c] = __floats2half2_rn(v0, v1);
            if (r1 < NN) *(__half2*)&g_h1h[(size_t)r1 * F1 + by * 64 + c] = __floats2half2_rn(v2, v3);
        }
        #pragma unroll
        for (int ofs = 1; ofs <= 2; ofs <<= 1) {
            ps0 += __shfl_xor_sync(0xffffffffu, ps0, ofs);
            pd0 += __shfl_xor_sync(0xffffffffu, pd0, ofs);
            ps1 += __shfl_xor_sync(0xffffffffu, ps1, ofs);
            pd1 += __shfl_xor_sync(0xffffffffu, pd1, ofs);
        }
        if (tig == 0) {
            if (r0 < NN) {
                atomicAdd(&g_al1s[r0 * 8 + by], ps0);
                atomicAdd(&g_al1d[r0 * 8 + by], pd0);
            }
            if (r1 < NN) {
                atomicAdd(&g_al1s[r1 * 8 + by], ps1);
                atomicAdd(&g_al1d[r1 * 8 + by], pd1);
            }
        }
    }
}

// ------------------------- layer-1 pass A: edge weights + denominators ------
__global__ __launch_bounds__(256) void k_agg1a() {
    int tid = threadIdx.x;
    int wid = tid >> 5, lane = tid & 31;
    int n = blockIdx.x * 8 + wid;
    int beg = g_off[n], end = g_off[n + 1];

    float ad[8];
    {
        const float4* p = (const float4*)&g_al1d[n * 8];
        float4 u = p[0], v = p[1];
        ad[0]=u.x; ad[1]=u.y; ad[2]=u.z; ad[3]=u.w; ad[4]=v.x; ad[5]=v.y; ad[6]=v.z; ad[7]=v.w;
    }
    float sm[8];
    #pragma unroll
    for (int hh = 0; hh < 8; hh++) sm[hh] = 0.f;

    for (int e = beg + lane; e < end; e += 32) {
        int s = g_esrc[e];
        const float4* q = (const float4*)&g_al1s[s * 8];
        float4 u = q[0], v = q[1];
        float wv[8];
        wv[0] = __expf(lrelu(u.x + ad[0]));
        wv[1] = __expf(lrelu(u.y + ad[1]));
        wv[2] = __expf(lrelu(u.z + ad[2]));
        wv[3] = __expf(lrelu(u.w + ad[3]));
        wv[4] = __expf(lrelu(v.x + ad[4]));
        wv[5] = __expf(lrelu(v.y + ad[5]));
        wv[6] = __expf(lrelu(v.z + ad[6]));
        wv[7] = __expf(lrelu(v.w + ad[7]));
        #pragma unroll
        for (int hh = 0; hh < 8; hh++) sm[hh] += wv[hh];
        float4* o = (float4*)&g_ew[(size_t)e * 8];
        o[0] = make_float4(wv[0], wv[2], wv[4], wv[6]);
        o[1] = make_float4(wv[1], wv[3], wv[5], wv[7]);
    }
    #pragma unroll
    for (int ofs = 16; ofs >= 1; ofs >>= 1)
        #pragma unroll
        for (int hh = 0; hh < 8; hh++) sm[hh] += __shfl_xor_sync(0xffffffffu, sm[hh], ofs);

    if (lane == 0) {
        float4* r = (float4*)&g_rs[n * 8];
        r[0] = make_float4(1.f / sm[0], 1.f / sm[2], 1.f / sm[4], 1.f / sm[6]);
        r[1] = make_float4(1.f / sm[1], 1.f / sm[3], 1.f / sm[5], 1.f / sm[7]);
    }
}

// ------------------------- layer-1 pass B: weighted gather + bias + ELU -----
__global__ __launch_bounds__(256) void k_agg1b(const float* __restrict__ b1) {
    __shared__ float sb1[F1];
    int tid = threadIdx.x;
    for (int i = tid; i < F1; i += 256) sb1[i] = b1[i];
    __syncthreads();
    int wid = tid >> 5, lane = tid & 31;
    int n = blockIdx.x * 8 + wid;
    int beg = g_off[n], end = g_off[n + 1];
    int hi = lane >> 4;

    float4 acc[4];
    #pragma unroll
    for (int j = 0; j < 4; j++) acc[j] = make_float4(0.f, 0.f, 0.f, 0.f);

    for (int e = beg; e < end; e++) {
        int s = g_esrc[e];
        float4 wv = *(const float4*)&g_ew[(size_t)e * 8 + hi * 4];
        float wa[4] = { wv.x, wv.y, wv.z, wv.w };
        const uint2* hp = (const uint2*)&g_h1h[(size_t)s * F1];
        #pragma unroll
        for (int j = 0; j < 4; j++) {
            uint2 hv = hp[lane + 32 * j];
            float2 f01 = __half22float2(*(__half2*)&hv.x);
            float2 f23 = __half22float2(*(__half2*)&hv.y);
            float a = wa[j];
            acc[j].x = fmaf(a, f01.x, acc[j].x);
            acc[j].y = fmaf(a, f01.y, acc[j].y);
            acc[j].z = fmaf(a, f23.x, acc[j].z);
            acc[j].w = fmaf(a, f23.y, acc[j].w);
        }
    }
    float4 rsv = *(const float4*)&g_rs[n * 8 + hi * 4];
    float ra[4] = { rsv.x, rsv.y, rsv.z, rsv.w };

    float4* op = (float4*)&g_out1[(size_t)n * F1];
    #pragma unroll
    for (int j = 0; j < 4; j++) {
        int ch = lane * 4 + 128 * j;
        float4 bb = *(float4*)&sb1[ch];
        float4 o;
        o.x = eluf(acc[j].x * ra[j] + bb.x);
        o.y = eluf(acc[j].y * ra[j] + bb.y);
        o.z = eluf(acc[j].z * ra[j] + bb.z);
        o.w = eluf(acc[j].w * ra[j] + bb.w);
        op[lane + 32 * j] = o;
    }
}

// ------------------------- GEMM2 + layer-2 attention halves -----------------
__global__ __launch_bounds__(256) void k_gemm2(const float* __restrict__ W2,
                                               const float* __restrict__ a2s,
                                               const float* __restrict__ a2d) {
    __shared__ __align__(16) float sw[F1 * 20];
    __shared__ float sa2s[16], sa2d[16];
    int tid = threadIdx.x;
    for (int i = tid; i < F1 * C2N; i += 256) {
        int k = i >> 4, o = i & 15;
        sw[k * 20 + o] = W2[i];
    }
    if (tid < 16) { sa2s[tid] = a2s[tid]; sa2d[tid] = a2d[tid]; }
    __syncthreads();
    int wid = tid >> 5, lane = tid & 31;
    int n0 = (blockIdx.x * 8 + wid) * 2;
    const float* vA = &g_out1[(size_t)n0 * F1];
    const float* vB = vA + F1;
    float4 pA[4], pB[4];
    #pragma unroll
    for (int q = 0; q < 4; q++) { pA[q] = make_float4(0,0,0,0); pB[q] = make_float4(0,0,0,0); }
    #pragma unroll
    for (int j = 0; j < 16; j++) {
        int k = lane + 32 * j;
        float a = vA[k], b = vB[k];
        const float4* wr = (const float4*)&sw[k * 20];
        #pragma unroll
        for (int q = 0; q < 4; q++) {
            float4 w = wr[q];
            pA[q].x = fmaf(a, w.x, pA[q].x); pA[q].y = fmaf(a, w.y, pA[q].y);
            pA[q].z = fmaf(a, w.z, pA[q].z); pA[q].w = fmaf(a, w.w, pA[q].w);
            pB[q].x = fmaf(b, w.x, pB[q].x); pB[q].y = fmaf(b, w.y, pB[q].y);
            pB[q].z = fmaf(b, w.z, pB[q].z); pB[q].w = fmaf(b, w.w, pB[q].w);
        }
    }
    #pragma unroll
    for (int o = 16; o >= 1; o >>= 1) {
        #pragma unroll
        for (int q = 0; q < 4; q++) {
            pA[q].x += __shfl_xor_sync(0xffffffffu, pA[q].x, o);
            pA[q].y += __shfl_xor_sync(0xffffffffu, pA[q].y, o);
            pA[q].z += __shfl_xor_sync(0xffffffffu, pA[q].z, o);
            pA[q].w += __shfl_xor_sync(0xffffffffu, pA[q].w, o);
            pB[q].x += __shfl_xor_sync(0xffffffffu, pB[q].x, o);
            pB[q].y += __shfl_xor_sync(0xffffffffu, pB[q].y, o);
            pB[q].z += __shfl_xor_sync(0xffffffffu, pB[q].z, o);
            pB[q].w += __shfl_xor_sync(0xffffffffu, pB[q].w, o);
        }
    }
    if (lane < 2) {
        int n = n0 + lane;
        float4 P[4];
        #pragma unroll
        for (int q = 0; q < 4; q++) P[q] = lane ? pB[q] : pA[q];
        float4* ho = (float4*)&g_h2[(size_t)n * C2N];
        #pragma unroll
        for (int q = 0; q < 4; q++) ho[q] = P[q];
        float ds = 0.f, dd = 0.f;
        #pragma unroll
        for (int q = 0; q < 4; q++) {
            ds += P[q].x * sa2s[q*4+0] + P[q].y * sa2s[q*4+1] + P[q].z * sa2s[q*4+2] + P[q].w * sa2s[q*4+3];
            dd += P[q].x * sa2d[q*4+0] + P[q].y * sa2d[q*4+1] + P[q].z * sa2d[q*4+2] + P[q].w * sa2d[q*4+3];
        }
        g_al2s[n] = ds;
        g_al2d[n] = dd;
    }
}

// ------------------------- layer-2 softmax + aggregation + bias -------------
__global__ __launch_bounds__(256) void k_agg2(const float* __restrict__ b2,
                                              float* __restrict__ out) {
    int tid = threadIdx.x;
    int wid = tid >> 5, lane = tid & 31;
    int n = blockIdx.x * 8 + wid;
    int beg = g_off[n], end = g_off[n + 1];
    float adn = g_al2d[n];

    float sm = 0.f;
    for (int e = beg + lane; e < end; e += 32) {
        int s = g_esrc[e];
        sm += __expf(lrelu(g_al2s[s] + adn));
    }
    #pragma unroll
    for (int o = 16; o >= 1; o >>= 1) sm += __shfl_xor_sync(0xffffffffu, sm, o);
    float rinv = 1.f / sm;

    int half = lane >> 4, hl = lane & 15;
    float acc = 0.f;
    for (int e2 = beg; e2 < end; e2 += 2) {
        int e = e2 + half;
        bool ok = (e < end);
        int s = 0;
        float av = 0.f;
        if (ok) s = g_esrc[e];
        if (ok && hl == 0) {
            float t = lrelu(g_al2s[s] + adn);
            av = __expf(t) * rinv;
        }
        av = __shfl_sync(0xffffffffu, av, half << 4);
        float v = ok ? g_h2[(size_t)s * C2N + hl] : 0.f;
        acc = fmaf(av, v, acc);
    }
    acc += __shfl_xor_sync(0xffffffffu, acc, 16);
    if (lane < 16) out[(size_t)n * C2N + lane] = acc + b2[lane];
}

// ------------------------- launch -------------------------------------------
extern "C" void kernel_launch(void* const* d_in, const int* in_sizes, int n_in,
                              void* d_out, int out_size) {
    const float* x   = (const float*)d_in[0];
    const int*   ei  = (const int*)  d_in[1];
    const float* W1  = (const float*)d_in[2];
    const float* a1s = (const float*)d_in[3];
    const float* a1d = (const float*)d_in[4];
    const float* b1  = (const float*)d_in[5];
    const float* W2  = (const float*)d_in[6];
    const float* a2s = (const float*)d_in[7];
    const float* a2d = (const float*)d_in[8];
    const float* b2  = (const float*)d_in[9];
    float* out = (float*)d_out;

    cudaFuncSetAttribute(k_gemm1_mma, cudaFuncAttributeMaxDynamicSharedMemorySize, G1_SMEM);

    k_prep_x<<<XT, 256>>>(x);                       // 0
    k_prep_w<<<4, 256>>>(W1);                       // 1
    k_zero<<<(NN * H1N + 255) / 256, 256>>>();      // 2 (also zeroes al1s/al1d)
    k_gemm1_mma<<<dim3(XT, 8), 256, G1_SMEM>>>(a1s, a1d);  // 3 -> profiled slot
    k_deg<<<(ET + 255) / 256, 256>>>(ei);           // 4
    k_scan1<<<49, 1024>>>();                        // 5
    k_scan2<<<1, 64>>>();                           // 6
    k_scan3<<<49, 1024>>>();                        // 7
    k_fill<<<(ET + 255) / 256, 256>>>(ei);          // 8
    k_agg1a<<<NN / 8, 256>>>();                     // 9
    k_agg1b<<<NN / 8, 256>>>(b1);                   // 10
    k_gemm2<<<NN / 16, 256>>>(W2, a2s, a2d);        // 11
    k_agg2<<<NN / 8, 256>>>(b2, out);               // 12
}